// round 10
// baseline (speedup 1.0000x reference)
#include <cuda_runtime.h>
#include <math.h>
#include <stdint.h>

#define B_  4
#define C_  256
#define CI_ 128
#define NQ_ 8192
#define NKV_ 2048

// scratch (no cudaMalloc allowed)
__device__ float d_xT  [(size_t)B_ * NQ_ * C_];     // (b, n, c)    tf32-rounded
__device__ float twr   [CI_ * C_];
__device__ float gwr   [CI_ * C_];
__device__ float pwr   [CI_ * C_];
__device__ float wwr   [C_ * CI_];
__device__ float d_theta[(size_t)B_ * NQ_ * CI_];   // (b, n, ci)   tf32-rounded
__device__ float d_key  [(size_t)B_ * NKV_ * CI_];  // (b, m, ci)   tf32-rounded
__device__ float d_valT [(size_t)B_ * CI_ * NKV_];  // (b, ci, m)   tf32-rounded
__device__ float d_yy   [(size_t)B_ * NQ_ * CI_];   // (b, n, ci)   tf32-rounded

__device__ __forceinline__ float f2tf(float f) {
    uint32_t u;
    asm("cvt.rna.tf32.f32 %0, %1;" : "=r"(u) : "f"(f));
    return __uint_as_float(u);
}

__device__ __forceinline__ void mma_tf32(float* c, const uint32_t* a, const uint32_t* b) {
    asm volatile(
        "mma.sync.aligned.m16n8k8.row.col.f32.tf32.tf32.f32 "
        "{%0,%1,%2,%3}, {%4,%5,%6,%7}, {%8,%9}, {%0,%1,%2,%3};"
        : "+f"(c[0]), "+f"(c[1]), "+f"(c[2]), "+f"(c[3])
        : "r"(a[0]), "r"(a[1]), "r"(a[2]), "r"(a[3]), "r"(b[0]), "r"(b[1]));
}

__device__ __forceinline__ void ldsm_x4(uint32_t* r, uint32_t a) {
    asm volatile("ldmatrix.sync.aligned.m8n8.x4.shared.b16 {%0,%1,%2,%3}, [%4];"
                 : "=r"(r[0]), "=r"(r[1]), "=r"(r[2]), "=r"(r[3]) : "r"(a));
}

__device__ __forceinline__ void cpa(uint32_t dst, const float* src) {
    asm volatile("cp.async.cg.shared.global [%0], [%1], 16;" :: "r"(dst), "l"(src));
}
#define CP_COMMIT() asm volatile("cp.async.commit_group;")
#define CP_WAIT0()  asm volatile("cp.async.wait_group 0;")

// ---------------------------------------------------------------------------
// Prep (merged): z<4 -> transpose+round x slice; z==4 -> round weights.
// grid (128, 4, 5), 256 threads.
// ---------------------------------------------------------------------------
__global__ void __launch_bounds__(256) prep_kernel(
        const float* __restrict__ x,
        const float* __restrict__ tw, const float* __restrict__ gw,
        const float* __restrict__ pw, const float* __restrict__ ww) {
    if (blockIdx.z == 4) {
        int bid = blockIdx.y * 128 + blockIdx.x;
        if (bid >= 32) return;
        int i = (bid * 256 + threadIdx.x) * 4;
        float4 v;
        v = *(const float4*)&tw[i];
        v.x = f2tf(v.x); v.y = f2tf(v.y); v.z = f2tf(v.z); v.w = f2tf(v.w);
        *(float4*)&twr[i] = v;
        v = *(const float4*)&gw[i];
        v.x = f2tf(v.x); v.y = f2tf(v.y); v.z = f2tf(v.z); v.w = f2tf(v.w);
        *(float4*)&gwr[i] = v;
        v = *(const float4*)&pw[i];
        v.x = f2tf(v.x); v.y = f2tf(v.y); v.z = f2tf(v.z); v.w = f2tf(v.w);
        *(float4*)&pwr[i] = v;
        v = *(const float4*)&ww[i];
        v.x = f2tf(v.x); v.y = f2tf(v.y); v.z = f2tf(v.z); v.w = f2tf(v.w);
        *(float4*)&wwr[i] = v;
        return;
    }
    __shared__ float Ts[64 * 65];
    const int b = blockIdx.z, cb = blockIdx.y * 64, nb = blockIdx.x * 64;
    const int tid = threadIdx.x;
#pragma unroll
    for (int u = 0; u < 4; u++) {
        int idx = u * 256 + tid;
        int cc = idx >> 4, j4 = idx & 15;
        float4 v = *(const float4*)&x[((size_t)b * C_ + cb + cc) * NQ_ + nb + j4 * 4];
        Ts[(j4 * 4 + 0) * 65 + cc] = f2tf(v.x);
        Ts[(j4 * 4 + 1) * 65 + cc] = f2tf(v.y);
        Ts[(j4 * 4 + 2) * 65 + cc] = f2tf(v.z);
        Ts[(j4 * 4 + 3) * 65 + cc] = f2tf(v.w);
    }
    __syncthreads();
#pragma unroll
    for (int u = 0; u < 4; u++) {
        int idx = u * 256 + tid;
        int nn = idx >> 4, c4 = idx & 15;
        float4 v = {Ts[nn * 65 + c4 * 4], Ts[nn * 65 + c4 * 4 + 1],
                    Ts[nn * 65 + c4 * 4 + 2], Ts[nn * 65 + c4 * 4 + 3]};
        *(float4*)&d_xT[((size_t)b * NQ_ + nb + nn) * C_ + cb + c4 * 4] = v;
    }
}

// ---------------------------------------------------------------------------
// Kernel A: theta conv. 64n x 128o, K=256 in 4 chunks, 2 blocks/SM. (R9)
// ---------------------------------------------------------------------------
__global__ void __launch_bounds__(256, 2) conv_theta_kernel(const float* __restrict__ tb) {
    extern __shared__ float sm[];
    const int b = blockIdx.y;
    const int nbase = blockIdx.x * 64;
    const int tid = threadIdx.x;
    const int warp = tid >> 5, lane = tid & 31;
    const int g = lane >> 2, q4 = lane & 3;
    const int m0 = (warp >> 2) * 32;
    const int n0 = (warp & 3) * 32;
    const uint32_t smb = (uint32_t)__cvta_generic_to_shared(sm);
    const uint32_t XB[2] = {0u, 4352u}, WB[2] = {8704u, 17408u};
    const int aOff = ((lane & 7) + ((lane >> 3) & 1) * 8) * 68 + ((lane >> 4) ? 4 : 0);
    const int bOff = ((lane & 7) + ((lane >> 4) & 1) * 8) * 68 + ((lane >> 3) & 1) * 4;

    float acc[2][4][4];
#pragma unroll
    for (int i = 0; i < 2; i++)
#pragma unroll
        for (int j = 0; j < 4; j++)
#pragma unroll
            for (int k = 0; k < 4; k++) acc[i][j][k] = 0.f;

    const float* xb = &d_xT[((size_t)b * NQ_ + nbase) * C_];

#pragma unroll
    for (int u = 0; u < 4; u++) {
        int idx = u * 256 + tid;
        int r = idx >> 4, c4 = idx & 15;
        cpa(smb + (XB[0] + r * 68 + c4 * 4) * 4u, xb + (size_t)r * C_ + c4 * 4);
    }
#pragma unroll
    for (int u = 0; u < 8; u++) {
        int idx = u * 256 + tid;
        int r = idx >> 4, c4 = idx & 15;
        cpa(smb + (WB[0] + r * 68 + c4 * 4) * 4u, &twr[r * C_ + c4 * 4]);
    }
    CP_COMMIT();

    for (int ch = 0; ch < 4; ch++) {
        CP_WAIT0();
        __syncthreads();
        if (ch < 3) {
            int c0 = (ch + 1) * 64, buf = (ch + 1) & 1;
#pragma unroll
            for (int u = 0; u < 4; u++) {
                int idx = u * 256 + tid;
                int r = idx >> 4, c4 = idx & 15;
                cpa(smb + (XB[buf] + r * 68 + c4 * 4) * 4u, xb + (size_t)r * C_ + c0 + c4 * 4);
            }
#pragma unroll
            for (int u = 0; u < 8; u++) {
                int idx = u * 256 + tid;
                int r = idx >> 4, c4 = idx & 15;
                cpa(smb + (WB[buf] + r * 68 + c4 * 4) * 4u, &twr[r * C_ + c0 + c4 * 4]);
            }
            CP_COMMIT();
        }
        const uint32_t Xa = smb + (XB[ch & 1] + aOff) * 4u;
        const uint32_t Wa = smb + (WB[ch & 1] + bOff) * 4u;
#pragma unroll
        for (int ks = 0; ks < 8; ks++) {
            uint32_t a[2][4];
#pragma unroll
            for (int mt = 0; mt < 2; mt++)
                ldsm_x4(a[mt], Xa + (uint32_t)((m0 + mt * 16) * 68 + ks * 8) * 4u);
#pragma unroll
            for (int np = 0; np < 2; np++) {
                uint32_t bb[4];
                ldsm_x4(bb, Wa + (uint32_t)((n0 + np * 16) * 68 + ks * 8) * 4u);
#pragma unroll
                for (int mt = 0; mt < 2; mt++) {
                    mma_tf32(acc[mt][2 * np], a[mt], bb);
                    mma_tf32(acc[mt][2 * np + 1], a[mt], bb + 2);
                }
            }
        }
    }
#pragma unroll
    for (int j = 0; j < 4; j++) {
        int o = n0 + j * 8 + 2 * q4;
        float b0 = tb[o], b1 = tb[o + 1];
#pragma unroll
        for (int mt = 0; mt < 2; mt++) {
            size_t r = (size_t)b * NQ_ + nbase + m0 + mt * 16 + g;
            float2 v0 = {f2tf(acc[mt][j][0] + b0), f2tf(acc[mt][j][1] + b1)};
            float2 v1 = {f2tf(acc[mt][j][2] + b0), f2tf(acc[mt][j][3] + b1)};
            *(float2*)&d_theta[r * CI_ + o] = v0;
            *(float2*)&d_theta[(r + 8) * CI_ + o] = v1;
        }
    }
}

// ---------------------------------------------------------------------------
// Kernel B: g/phi conv + maxpool. 64n x 64o (o-split), 2 blocks/SM. (R9)
// ---------------------------------------------------------------------------
__global__ void __launch_bounds__(256, 2) conv_gphi_kernel(
        const float* __restrict__ gb, const float* __restrict__ pb) {
    extern __shared__ float sm[];
    const int b = blockIdx.z;
    const int ob = blockIdx.y;
    const int t = blockIdx.x >> 4, hp = blockIdx.x & 15;
    const int nbase = t * 1024 + hp * 64;
    const int tid = threadIdx.x;
    const int warp = tid >> 5, lane = tid & 31;
    const int g = lane >> 2, q4 = lane & 3;
    const int m0 = (warp >> 2) * 32;
    const int n0 = (warp & 3) * 16;
    const uint32_t smb = (uint32_t)__cvta_generic_to_shared(sm);
    const uint32_t XB[2] = {0u, 4352u}, GB[2] = {8704u, 13056u}, PB[2] = {17408u, 21760u};
    const int aOff = ((lane & 7) + ((lane >> 3) & 1) * 8) * 68 + ((lane >> 4) ? 4 : 0);
    const int bOff = ((lane & 7) + ((lane >> 4) & 1) * 8) * 68 + ((lane >> 3) & 1) * 4;

    float ag[2][2][4], ap[2][2][4];
#pragma unroll
    for (int i = 0; i < 2; i++)
#pragma unroll
        for (int j = 0; j < 2; j++)
#pragma unroll
            for (int k = 0; k < 4; k++) { ag[i][j][k] = 0.f; ap[i][j][k] = 0.f; }

    const float* xb = &d_xT[((size_t)b * NQ_ + nbase) * C_];
    const float* gwb = &gwr[(ob * 64) * C_];
    const float* pwb = &pwr[(ob * 64) * C_];

#pragma unroll
    for (int u = 0; u < 4; u++) {
        int idx = u * 256 + tid;
        int r = idx >> 4, c4 = idx & 15;
        cpa(smb + (XB[0] + r * 68 + c4 * 4) * 4u, xb + (size_t)r * C_ + c4 * 4);
        cpa(smb + (GB[0] + r * 68 + c4 * 4) * 4u, gwb + r * C_ + c4 * 4);
        cpa(smb + (PB[0] + r * 68 + c4 * 4) * 4u, pwb + r * C_ + c4 * 4);
    }
    CP_COMMIT();

    for (int ch = 0; ch < 4; ch++) {
        CP_WAIT0();
        __syncthreads();
        if (ch < 3) {
            int c0 = (ch + 1) * 64, buf = (ch + 1) & 1;
#pragma unroll
            for (int u = 0; u < 4; u++) {
                int idx = u * 256 + tid;
                int r = idx >> 4, c4 = idx & 15;
                cpa(smb + (XB[buf] + r * 68 + c4 * 4) * 4u, xb + (size_t)r * C_ + c0 + c4 * 4);
                cpa(smb + (GB[buf] + r * 68 + c4 * 4) * 4u, gwb + r * C_ + c0 + c4 * 4);
                cpa(smb + (PB[buf] + r * 68 + c4 * 4) * 4u, pwb + r * C_ + c0 + c4 * 4);
            }
            CP_COMMIT();
        }
        const uint32_t Xa = smb + (XB[ch & 1] + aOff) * 4u;
        const uint32_t Ga = smb + (GB[ch & 1] + bOff) * 4u;
        const uint32_t Pa = smb + (PB[ch & 1] + bOff) * 4u;
#pragma unroll
        for (int ks = 0; ks < 8; ks++) {
            uint32_t a[2][4];
#pragma unroll
            for (int mt = 0; mt < 2; mt++)
                ldsm_x4(a[mt], Xa + (uint32_t)((m0 + mt * 16) * 68 + ks * 8) * 4u);
            uint32_t bg_[4], bp_[4];
            ldsm_x4(bg_, Ga + (uint32_t)(n0 * 68 + ks * 8) * 4u);
            ldsm_x4(bp_, Pa + (uint32_t)(n0 * 68 + ks * 8) * 4u);
#pragma unroll
            for (int mt = 0; mt < 2; mt++) {
                mma_tf32(ag[mt][0], a[mt], bg_);
                mma_tf32(ag[mt][1], a[mt], bg_ + 2);
                mma_tf32(ap[mt][0], a[mt], bp_);
                mma_tf32(ap[mt][1], a[mt], bp_ + 2);
            }
        }
    }
    __syncthreads();
    float* Sg = sm;
    float* Sp = sm + 4352;
    float* Pv = sm + 2 * 4352;
#pragma unroll
    for (int mt = 0; mt < 2; mt++) {
#pragma unroll
        for (int j = 0; j < 2; j++) {
            int r = m0 + mt * 16 + g;
            int o = n0 + j * 8 + 2 * q4;
            *(float2*)&Sg[r * 68 + o] = *(float2*)&ag[mt][j][0];
            *(float2*)&Sg[(r + 8) * 68 + o] = *(float2*)&ag[mt][j][2];
            *(float2*)&Sp[r * 68 + o] = *(float2*)&ap[mt][j][0];
            *(float2*)&Sp[(r + 8) * 68 + o] = *(float2*)&ap[mt][j][2];
        }
    }
    __syncthreads();
    const int mb = t * 256 + hp * 16;
    {
        int p = tid >> 4, o4 = (tid & 15) * 4;
        float4 bgv = *(const float4*)&gb[ob * 64 + o4];
        float4 bpv = *(const float4*)&pb[ob * 64 + o4];
        float4 r0, r1, r2, r3;
        r0 = *(float4*)&Sp[(2 * p) * 68 + o4];
        r1 = *(float4*)&Sp[(2 * p + 1) * 68 + o4];
        r2 = *(float4*)&Sp[(32 + 2 * p) * 68 + o4];
        r3 = *(float4*)&Sp[(33 + 2 * p) * 68 + o4];
        float4 ko;
        ko.x = f2tf(fmaxf(fmaxf(r0.x, r1.x), fmaxf(r2.x, r3.x)) + bpv.x);
        ko.y = f2tf(fmaxf(fmaxf(r0.y, r1.y), fmaxf(r2.y, r3.y)) + bpv.y);
        ko.z = f2tf(fmaxf(fmaxf(r0.z, r1.z), fmaxf(r2.z, r3.z)) + bpv.z);
        ko.w = f2tf(fmaxf(fmaxf(r0.w, r1.w), fmaxf(r2.w, r3.w)) + bpv.w);
        *(float4*)&d_key[((size_t)b * NKV_ + mb + p) * CI_ + ob * 64 + o4] = ko;
        r0 = *(float4*)&Sg[(2 * p) * 68 + o4];
        r1 = *(float4*)&Sg[(2 * p + 1) * 68 + o4];
        r2 = *(float4*)&Sg[(32 + 2 * p) * 68 + o4];
        r3 = *(float4*)&Sg[(33 + 2 * p) * 68 + o4];
        Pv[(o4 + 0) * 20 + p] = f2tf(fmaxf(fmaxf(r0.x, r1.x), fmaxf(r2.x, r3.x)) + bgv.x);
        Pv[(o4 + 1) * 20 + p] = f2tf(fmaxf(fmaxf(r0.y, r1.y), fmaxf(r2.y, r3.y)) + bgv.y);
        Pv[(o4 + 2) * 20 + p] = f2tf(fmaxf(fmaxf(r0.z, r1.z), fmaxf(r2.z, r3.z)) + bgv.z);
        Pv[(o4 + 3) * 20 + p] = f2tf(fmaxf(fmaxf(r0.w, r1.w), fmaxf(r2.w, r3.w)) + bgv.w);
    }
    __syncthreads();
    {
        int ci = tid >> 2, j = (tid & 3) * 4;
        float4 v = {Pv[ci * 20 + j], Pv[ci * 20 + j + 1],
                    Pv[ci * 20 + j + 2], Pv[ci * 20 + j + 3]};
        *(float4*)&d_valT[((size_t)b * CI_ + ob * 64 + ci) * NKV_ + mb + j] = v;
    }
}

// ---------------------------------------------------------------------------
// Kernel C: flash attention, BQ=64, BK=32, fixed-m̂, 2 blocks/SM.
// grid (NQ/64, B), 256 threads (8 warps: mt4=warp&3 -> q rows 16*mt4,
// nh=warp>>2 -> kv/d half).
// smem floats: Q@0 [64][132]=8448; K0@8448 K1@12672 [32][132]=4224;
//   V0@16896 V1@21504 [128][36]=4608; Ps@26112 [64][36]=2304. 28416 fl=111KB.
// ---------------------------------------------------------------------------
__device__ __forceinline__ void attn_prefetch(uint32_t smb, uint32_t kb, uint32_t vb,
        const float* __restrict__ keyb, const float* __restrict__ valb,
        int mbase, int tid) {
#pragma unroll
    for (int u = 0; u < 4; u++) {
        int idx = u * 256 + tid;
        int r = idx >> 5, c = idx & 31;
        cpa(smb + (kb + r * 132 + c * 4) * 4u, keyb + (size_t)(mbase + r) * CI_ + c * 4);
    }
#pragma unroll
    for (int u = 0; u < 4; u++) {
        int idx = u * 256 + tid;
        int r = idx >> 3, c = idx & 7;
        cpa(smb + (vb + r * 36 + c * 4) * 4u, valb + (size_t)r * NKV_ + mbase + c * 4);
    }
}

__global__ void __launch_bounds__(256, 2) attn_kernel() {
    extern __shared__ float sm[];
    const int b = blockIdx.y;
    const int qbase = blockIdx.x * 64;
    const int tid = threadIdx.x;
    const int warp = tid >> 5, lane = tid & 31;
    const int g = lane >> 2, q4 = lane & 3;
    const int mt4 = warp & 3, nh = warp >> 2;
    const int r0w = mt4 * 16;
    const uint32_t smb = (uint32_t)__cvta_generic_to_shared(sm);
    const uint32_t QO = 0u, KO[2] = {8448u, 12672u}, VO[2] = {16896u, 21504u}, PO = 26112u;
    float* Ps = sm + PO;
    float* red = sm + PO;   // reused (disjoint in time from Ps use)

    const int aQ = ((lane & 7) + ((lane >> 3) & 1) * 8) * 132 + ((lane >> 4) ? 4 : 0);
    const int bK = ((lane & 7) + ((lane >> 4) & 1) * 8) * 132 + ((lane >> 3) & 1) * 4;
    const int aP = ((lane & 7) + ((lane >> 3) & 1) * 8) * 36 + ((lane >> 4) ? 4 : 0);
    const int bV = ((lane & 7) + ((lane >> 4) & 1) * 8) * 36 + ((lane >> 3) & 1) * 4;

    const float* qb = &d_theta[((size_t)b * NQ_ + qbase) * CI_];
    const float* keyb = &d_key[(size_t)b * NKV_ * CI_];
    const float* valb = &d_valT[(size_t)b * CI_ * NKV_];

    // prologue: Q + K0/V0
#pragma unroll
    for (int u = 0; u < 8; u++) {
        int idx = u * 256 + tid;
        int r = idx >> 5, c = idx & 31;
        cpa(smb + (QO + r * 132 + c * 4) * 4u, qb + (size_t)r * CI_ + c * 4);
    }
    attn_prefetch(smb, KO[0], VO[0], keyb, valb, 0, tid);
    CP_COMMIT();

    float mhat[2] = {0.f, 0.f}, lsum[2] = {0.f, 0.f};
    float oacc[8][4];
#pragma unroll
    for (int i = 0; i < 8; i++)
#pragma unroll
        for (int j = 0; j < 4; j++) oacc[i][j] = 0.f;

    for (int mt = 0; mt < NKV_ / 32; mt++) {
        CP_WAIT0();
        __syncthreads();
        if (mt + 1 < NKV_ / 32) {
            attn_prefetch(smb, KO[(mt + 1) & 1], VO[(mt + 1) & 1], keyb, valb,
                          (mt + 1) * 32, tid);
            CP_COMMIT();
        }

        // S = Q K^T : 16 rows x 16 cols (2 n-tiles), k=128
        float sacc[2][4];
#pragma unroll
        for (int i = 0; i < 2; i++)
#pragma unroll
            for (int j = 0; j < 4; j++) sacc[i][j] = 0.f;
#pragma unroll
        for (int ks = 0; ks < 16; ks++) {
            uint32_t a[4], bb[4];
            ldsm_x4(a, smb + (uint32_t)(QO + r0w * 132 + aQ + ks * 8) * 4u);
            ldsm_x4(bb, smb + (uint32_t)(KO[mt & 1] + nh * 16 * 132 + bK + ks * 8) * 4u);
            mma_tf32(sacc[0], a, bb);
            mma_tf32(sacc[1], a, bb + 2);
        }

        if (mt == 0) {
            float mx0 = fmaxf(fmaxf(sacc[0][0], sacc[0][1]), fmaxf(sacc[1][0], sacc[1][1]));
            float mx1 = fmaxf(fmaxf(sacc[0][2], sacc[0][3]), fmaxf(sacc[1][2], sacc[1][3]));
            mx0 = fmaxf(mx0, __shfl_xor_sync(0xffffffffu, mx0, 1));
            mx0 = fmaxf(mx0, __shfl_xor_sync(0xffffffffu, mx0, 2));
            mx1 = fmaxf(mx1, __shfl_xor_sync(0xffffffffu, mx1, 1));
            mx1 = fmaxf(mx1, __shfl_xor_sync(0xffffffffu, mx1, 2));
            red[nh * 64 + r0w + g] = mx0;
            red[nh * 64 + r0w + 8 + g] = mx1;
            __syncthreads();
            mhat[0] = fmaxf(red[r0w + g], red[64 + r0w + g]);
            mhat[1] = fmaxf(red[r0w + 8 + g], red[64 + r0w + 8 + g]);
            __syncthreads();
        }

        // exp + P write
#pragma unroll
        for (int nt = 0; nt < 2; nt++) {
            float e0 = __expf(sacc[nt][0] - mhat[0]);
            float e1 = __expf(sacc[nt][1] - mhat[0]);
            float e2 = __expf(sacc[nt][2] - mhat[1]);
            float e3 = __expf(sacc[nt][3] - mhat[1]);
            lsum[0] += e0 + e1;
            lsum[1] += e2 + e3;
            int cb = nh * 16 + nt * 8 + 2 * q4;
            float2 v0 = {f2tf(e0), f2tf(e1)};
            float2 v1 = {f2tf(e2), f2tf(e3)};
            *(float2*)&Ps[(r0w + g) * 36 + cb] = v0;
            *(float2*)&Ps[(r0w + 8 + g) * 36 + cb] = v1;
        }
        __syncthreads();

        // O += P V : 16 rows x 64 d-cols (8 n-tiles), k=32
#pragma unroll
        for (int ks = 0; ks < 4; ks++) {
            uint32_t a[4];
            ldsm_x4(a, smb + (uint32_t)(PO + r0w * 36 + aP + ks * 8) * 4u);
#pragma unroll
            for (int np = 0; np < 4; np++) {
                uint32_t bb[4];
                ldsm_x4(bb, smb + (uint32_t)(VO[mt & 1] + (nh * 64 + np * 16) * 36
                                             + bV + ks * 8) * 4u);
                mma_tf32(oacc[2 * np], a, bb);
                mma_tf32(oacc[2 * np + 1], a, bb + 2);
            }
        }
    }

    // final l: quad-reduce (16 cols of this warp), then combine halves via smem
    __syncthreads();
#pragma unroll
    for (int h = 0; h < 2; h++) {
        lsum[h] += __shfl_xor_sync(0xffffffffu, lsum[h], 1);
        lsum[h] += __shfl_xor_sync(0xffffffffu, lsum[h], 2);
    }
    red[nh * 64 + r0w + g] = lsum[0];
    red[nh * 64 + r0w + 8 + g] = lsum[1];
    __syncthreads();
    float inv0 = 1.f / (red[r0w + g] + red[64 + r0w + g]);
    float inv1 = 1.f / (red[r0w + 8 + g] + red[64 + r0w + 8 + g]);

    size_t row0 = (size_t)b * NQ_ + qbase + r0w + g;
#pragma unroll
    for (int nt = 0; nt < 8; nt++) {
        int ci = nh * 64 + nt * 8 + 2 * q4;
        float2 v0 = {f2tf(oacc[nt][0] * inv0), f2tf(oacc[nt][1] * inv0)};
        float2 v1 = {f2tf(oacc[nt][2] * inv1), f2tf(oacc[nt][3] * inv1)};
        *(float2*)&d_yy[row0 * CI_ + ci] = v0;
        *(float2*)&d_yy[(row0 + 8) * CI_ + ci] = v1;
    }
}

// ---------------------------------------------------------------------------
// Kernel D: wconv + BN + residual. 128co x 64n, 2 blocks/SM. (R9)
// ---------------------------------------------------------------------------
__global__ void __launch_bounds__(256, 2) wconv_kernel(
        const float* __restrict__ x,
        const float* __restrict__ wb,
        const float* __restrict__ bng, const float* __restrict__ bnb,
        const float* __restrict__ bnm, const float* __restrict__ bnv,
        float* __restrict__ out) {
    extern __shared__ float sm[];
    const int b = blockIdx.z;
    const int cobase = blockIdx.y * 128;
    const int nbase = blockIdx.x * 64;
    const int tid = threadIdx.x;
    const int warp = tid >> 5, lane = tid & 31;
    const int g = lane >> 2, q4 = lane & 3;
    const int m0 = (warp >> 1) * 32;
    const int n0 = (warp & 1) * 32;
    const uint32_t smb = (uint32_t)__cvta_generic_to_shared(sm);
    const uint32_t WB[2] = {0u, 8704u}, YB[2] = {17408u, 21760u};
    const int aOff = ((lane & 7) + ((lane >> 3) & 1) * 8) * 68 + ((lane >> 4) ? 4 : 0);
    const int bOff = ((lane & 7) + ((lane >> 4) & 1) * 8) * 68 + ((lane >> 3) & 1) * 4;

    float acc[2][4][4];
#pragma unroll
    for (int i = 0; i < 2; i++)
#pragma unroll
        for (int j = 0; j < 4; j++)
#pragma unroll
            for (int k = 0; k < 4; k++) acc[i][j][k] = 0.f;

    const float* yb = &d_yy[((size_t)b * NQ_ + nbase) * CI_];

#pragma unroll
    for (int u = 0; u < 8; u++) {
        int idx = u * 256 + tid;
        int r = idx >> 4, c4 = idx & 15;
        cpa(smb + (WB[0] + r * 68 + c4 * 4) * 4u, &wwr[(cobase + r) * CI_ + c4 * 4]);
    }
#pragma unroll
    for (int u = 0; u < 4; u++) {
        int idx = u * 256 + tid;
        int r = idx >> 4, c4 = idx & 15;
        cpa(smb + (YB[0] + r * 68 + c4 * 4) * 4u, yb + (size_t)r * CI_ + c4 * 4);
    }
    CP_COMMIT();

    for (int ch = 0; ch < 2; ch++) {
        CP_WAIT0();
        __syncthreads();
        if (ch < 1) {
#pragma unroll
            for (int u = 0; u < 8; u++) {
                int idx = u * 256 + tid;
                int r = idx >> 4, c4 = idx & 15;
                cpa(smb + (WB[1] + r * 68 + c4 * 4) * 4u, &wwr[(cobase + r) * CI_ + 64 + c4 * 4]);
            }
#pragma unroll
            for (int u = 0; u < 4; u++) {
                int idx = u * 256 + tid;
                int r = idx >> 4, c4 = idx & 15;
                cpa(smb + (YB[1] + r * 68 + c4 * 4) * 4u, yb + (size_t)r * CI_ + 64 + c4 * 4);
            }
            CP_COMMIT();
        }
        const uint32_t Wa = smb + (WB[ch & 1] + aOff) * 4u;
        const uint32_t Ya = smb + (YB[ch & 1] + bOff) * 4u;
#pragma unroll
        for (int ks = 0; ks < 8; ks++) {
            uint32_t a[2][4];
#pragma unroll
            for (int mt = 0; mt < 2; mt++)
                ldsm_x4(a[mt], Wa + (uint32_t)((m0 + mt * 16) * 68 + ks * 8) * 4u);
#pragma unroll
            for (int np = 0; np < 2; np++) {
                uint32_t bb[4];
                ldsm_x4(bb, Ya + (uint32_t)((n0 + np * 16) * 68 + ks * 8) * 4u);
#pragma unroll
                for (int mt = 0; mt < 2; mt++) {
                    mma_tf32(acc[mt][2 * np], a[mt], bb);
                    mma_tf32(acc[mt][2 * np + 1], a[mt], bb + 2);
                }
            }
        }
    }

    float sc[2][2], sh[2][2];
#pragma unroll
    for (int mt = 0; mt < 2; mt++)
#pragma unroll
        for (int h = 0; h < 2; h++) {
            int co = cobase + m0 + mt * 16 + g + h * 8;
            float s = bng[co] * rsqrtf(bnv[co] + 1e-5f);
            sc[mt][h] = s;
            sh[mt][h] = bnb[co] - bnm[co] * s + s * wb[co];
        }
#pragma unroll
    for (int mt = 0; mt < 2; mt++) {
#pragma unroll
        for (int j = 0; j < 4; j++) {
            int n = nbase + n0 + j * 8 + 2 * q4;
#pragma unroll
            for (int h = 0; h < 2; h++) {
                int co = cobase + m0 + mt * 16 + g + h * 8;
                size_t base = ((size_t)b * C_ + co) * NQ_ + n;
                float2 xv = *(const float2*)&x[base];
                float2 o;
                o.x = acc[mt][j][2 * h]     * sc[mt][h] + sh[mt][h] + xv.x;
                o.y = acc[mt][j][2 * h + 1] * sc[mt][h] + sh[mt][h] + xv.y;
                *(float2*)&out[base] = o;
            }
        }
    }
}

// ---------------------------------------------------------------------------
extern "C" void kernel_launch(void* const* d_in, const int* in_sizes, int n_in,
                              void* d_out, int out_size) {
    const float* x    = (const float*)d_in[0];
    const float* g_w  = (const float*)d_in[1];
    const float* g_b  = (const float*)d_in[2];
    const float* th_w = (const float*)d_in[3];
    const float* th_b = (const float*)d_in[4];
    const float* ph_w = (const float*)d_in[5];
    const float* ph_b = (const float*)d_in[6];
    const float* w_w  = (const float*)d_in[7];
    const float* w_b  = (const float*)d_in[8];
    const float* bn_g = (const float*)d_in[9];
    const float* bn_b = (const float*)d_in[10];
    const float* bn_m = (const float*)d_in[11];
    const float* bn_v = (const float*)d_in[12];
    float* out = (float*)d_out;

    const int smA = 26112 * 4;   // 104448
    const int smB = 26112 * 4;   // 104448
    const int smC = 28416 * 4;   // 113664
    const int smD = 26112 * 4;   // 104448

    cudaFuncSetAttribute(conv_theta_kernel, cudaFuncAttributeMaxDynamicSharedMemorySize, smA);
    cudaFuncSetAttribute(conv_gphi_kernel,  cudaFuncAttributeMaxDynamicSharedMemorySize, smB);
    cudaFuncSetAttribute(attn_kernel,       cudaFuncAttributeMaxDynamicSharedMemorySize, smC);
    cudaFuncSetAttribute(wconv_kernel,      cudaFuncAttributeMaxDynamicSharedMemorySize, smD);

    prep_kernel<<<dim3(128, 4, 5), 256>>>(x, th_w, g_w, ph_w, w_w);
    conv_theta_kernel<<<dim3(NQ_ / 64, B_), 256, smA>>>(th_b);
    conv_gphi_kernel<<<dim3(128, 2, B_), 256, smB>>>(g_b, ph_b);
    attn_kernel<<<dim3(NQ_ / 64, B_), 256, smC>>>();
    wconv_kernel<<<dim3(NQ_ / 64, 2, B_), 256, smD>>>(x, w_b,
                                                      bn_g, bn_b, bn_m, bn_v, out);
}

// round 11
// speedup vs baseline: 1.8946x; 1.8946x over previous
#include <cuda_runtime.h>
#include <cuda_fp16.h>
#include <math.h>
#include <stdint.h>

#define B_  4
#define C_  256
#define CI_ 128
#define NQ_ 8192
#define NKV_ 2048

// scratch (no cudaMalloc allowed) — all fp16 payloads stored as u16
__device__ unsigned short d_xT  [(size_t)B_ * NQ_ * C_];   // (b, n, c)
__device__ unsigned short twr   [CI_ * C_];
__device__ unsigned short gwr   [CI_ * C_];
__device__ unsigned short pwr   [CI_ * C_];
__device__ unsigned short wwr   [C_ * CI_];
__device__ unsigned short d_theta[(size_t)B_ * NQ_ * CI_]; // (b, n, ci)
__device__ unsigned short d_key  [(size_t)B_ * NKV_ * CI_];// (b, m, ci)
__device__ unsigned short d_valT [(size_t)B_ * CI_ * NKV_];// (b, ci, m)
__device__ unsigned short d_yy   [(size_t)B_ * NQ_ * CI_]; // (b, n, ci)

__device__ __forceinline__ uint32_t f2h2(float lo, float hi) {
    uint32_t r;
    asm("cvt.rn.f16x2.f32 %0, %1, %2;" : "=r"(r) : "f"(hi), "f"(lo));
    return r;
}

__device__ __forceinline__ void mma_f16(float* c, const uint32_t* a,
                                        uint32_t b0, uint32_t b1) {
    asm volatile(
        "mma.sync.aligned.m16n8k16.row.col.f32.f16.f16.f32 "
        "{%0,%1,%2,%3}, {%4,%5,%6,%7}, {%8,%9}, {%0,%1,%2,%3};"
        : "+f"(c[0]), "+f"(c[1]), "+f"(c[2]), "+f"(c[3])
        : "r"(a[0]), "r"(a[1]), "r"(a[2]), "r"(a[3]), "r"(b0), "r"(b1));
}

__device__ __forceinline__ void ldsm_x4(uint32_t* r, uint32_t a) {
    asm volatile("ldmatrix.sync.aligned.m8n8.x4.shared.b16 {%0,%1,%2,%3}, [%4];"
                 : "=r"(r[0]), "=r"(r[1]), "=r"(r[2]), "=r"(r[3]) : "r"(a));
}

__device__ __forceinline__ void cpa(uint32_t dst, const void* src) {
    asm volatile("cp.async.cg.shared.global [%0], [%1], 16;" :: "r"(dst), "l"(src));
}
#define CP_COMMIT() asm volatile("cp.async.commit_group;")
#define CP_WAIT0()  asm volatile("cp.async.wait_group 0;")

// fragment base offsets (in halves): A/B tiles, row = lane&15, k-half = lane>>4
#define FRAG_OFF(stride) ((lane & 15) * (stride) + (lane >> 4) * 8)

// ---------------------------------------------------------------------------
// Prep: z<4 -> transpose+round x slice to fp16; z==4 -> round weights.
// grid (128, 4, 5), 256 threads.
// ---------------------------------------------------------------------------
__global__ void __launch_bounds__(256) prep_kernel(
        const float* __restrict__ x,
        const float* __restrict__ tw, const float* __restrict__ gw,
        const float* __restrict__ pw, const float* __restrict__ ww) {
    if (blockIdx.z == 4) {
        int bid = blockIdx.y * 128 + blockIdx.x;
        if (bid >= 16) return;
        int i = (bid * 256 + threadIdx.x) * 8;
        float4 v0, v1;
        uint2 o;
        v0 = *(const float4*)&tw[i]; v1 = *(const float4*)&tw[i + 4];
        o.x = f2h2(v0.x, v0.y); o.y = f2h2(v0.z, v0.w);
        *(uint2*)&twr[i] = o;
        o.x = f2h2(v1.x, v1.y); o.y = f2h2(v1.z, v1.w);
        *(uint2*)&twr[i + 4] = o;
        v0 = *(const float4*)&gw[i]; v1 = *(const float4*)&gw[i + 4];
        o.x = f2h2(v0.x, v0.y); o.y = f2h2(v0.z, v0.w);
        *(uint2*)&gwr[i] = o;
        o.x = f2h2(v1.x, v1.y); o.y = f2h2(v1.z, v1.w);
        *(uint2*)&gwr[i + 4] = o;
        v0 = *(const float4*)&pw[i]; v1 = *(const float4*)&pw[i + 4];
        o.x = f2h2(v0.x, v0.y); o.y = f2h2(v0.z, v0.w);
        *(uint2*)&pwr[i] = o;
        o.x = f2h2(v1.x, v1.y); o.y = f2h2(v1.z, v1.w);
        *(uint2*)&pwr[i + 4] = o;
        v0 = *(const float4*)&ww[i]; v1 = *(const float4*)&ww[i + 4];
        o.x = f2h2(v0.x, v0.y); o.y = f2h2(v0.z, v0.w);
        *(uint2*)&wwr[i] = o;
        o.x = f2h2(v1.x, v1.y); o.y = f2h2(v1.z, v1.w);
        *(uint2*)&wwr[i + 4] = o;
        return;
    }
    __shared__ float Ts[64 * 65];
    const int b = blockIdx.z, cb = blockIdx.y * 64, nb = blockIdx.x * 64;
    const int tid = threadIdx.x;
#pragma unroll
    for (int u = 0; u < 4; u++) {
        int idx = u * 256 + tid;
        int cc = idx >> 4, j4 = idx & 15;
        float4 v = *(const float4*)&x[((size_t)b * C_ + cb + cc) * NQ_ + nb + j4 * 4];
        Ts[(j4 * 4 + 0) * 65 + cc] = v.x;
        Ts[(j4 * 4 + 1) * 65 + cc] = v.y;
        Ts[(j4 * 4 + 2) * 65 + cc] = v.z;
        Ts[(j4 * 4 + 3) * 65 + cc] = v.w;
    }
    __syncthreads();
#pragma unroll
    for (int u = 0; u < 4; u++) {
        int idx = u * 256 + tid;
        int nn = idx >> 4, c4 = idx & 15;
        uint2 o;
        o.x = f2h2(Ts[nn * 65 + c4 * 4], Ts[nn * 65 + c4 * 4 + 1]);
        o.y = f2h2(Ts[nn * 65 + c4 * 4 + 2], Ts[nn * 65 + c4 * 4 + 3]);
        *(uint2*)&d_xT[((size_t)b * NQ_ + nb + nn) * C_ + cb + c4 * 4] = o;
    }
}

// ---------------------------------------------------------------------------
// Kernel A: theta conv fp16. 64n x 128o, K=256 in 4 chunks, 2 blocks/SM.
// smem halves: X0@0 X1@4608 ([64][72]); W0@9216 W1@18432 ([128][72]). 55296 B.
// ---------------------------------------------------------------------------
__global__ void __launch_bounds__(256, 2) conv_theta_kernel(const float* __restrict__ tb) {
    extern __shared__ unsigned short smh[];
    const int b = blockIdx.y;
    const int nbase = blockIdx.x * 64;
    const int tid = threadIdx.x;
    const int warp = tid >> 5, lane = tid & 31;
    const int g = lane >> 2, q4 = lane & 3;
    const int m0 = (warp >> 2) * 32;
    const int n0 = (warp & 3) * 32;
    const uint32_t smb = (uint32_t)__cvta_generic_to_shared(smh);
    const uint32_t XB[2] = {0u, 4608u}, WB[2] = {9216u, 18432u};
    const int fOff = FRAG_OFF(72);

    float acc[2][4][4];
#pragma unroll
    for (int i = 0; i < 2; i++)
#pragma unroll
        for (int j = 0; j < 4; j++)
#pragma unroll
            for (int k = 0; k < 4; k++) acc[i][j][k] = 0.f;

    const unsigned short* xb = d_xT + ((size_t)b * NQ_ + nbase) * C_;

#pragma unroll
    for (int u = 0; u < 2; u++) {
        int idx = u * 256 + tid;
        int r = idx >> 3, c8 = idx & 7;
        cpa(smb + (XB[0] + r * 72 + c8 * 8) * 2u, xb + (size_t)r * C_ + c8 * 8);
    }
#pragma unroll
    for (int u = 0; u < 4; u++) {
        int idx = u * 256 + tid;
        int r = idx >> 3, c8 = idx & 7;
        cpa(smb + (WB[0] + r * 72 + c8 * 8) * 2u, &twr[r * C_ + c8 * 8]);
    }
    CP_COMMIT();

    for (int ch = 0; ch < 4; ch++) {
        CP_WAIT0();
        __syncthreads();
        if (ch < 3) {
            int c0 = (ch + 1) * 64, buf = (ch + 1) & 1;
#pragma unroll
            for (int u = 0; u < 2; u++) {
                int idx = u * 256 + tid;
                int r = idx >> 3, c8 = idx & 7;
                cpa(smb + (XB[buf] + r * 72 + c8 * 8) * 2u, xb + (size_t)r * C_ + c0 + c8 * 8);
            }
#pragma unroll
            for (int u = 0; u < 4; u++) {
                int idx = u * 256 + tid;
                int r = idx >> 3, c8 = idx & 7;
                cpa(smb + (WB[buf] + r * 72 + c8 * 8) * 2u, &twr[r * C_ + c0 + c8 * 8]);
            }
            CP_COMMIT();
        }
#pragma unroll
        for (int ks = 0; ks < 4; ks++) {
            uint32_t a[2][4];
#pragma unroll
            for (int mt = 0; mt < 2; mt++)
                ldsm_x4(a[mt], smb + (uint32_t)(XB[ch & 1] + (m0 + mt * 16) * 72
                                                + ks * 16 + fOff) * 2u);
#pragma unroll
            for (int np = 0; np < 2; np++) {
                uint32_t bb[4];
                ldsm_x4(bb, smb + (uint32_t)(WB[ch & 1] + (n0 + np * 16) * 72
                                             + ks * 16 + fOff) * 2u);
#pragma unroll
                for (int mt = 0; mt < 2; mt++) {
                    mma_f16(acc[mt][2 * np], a[mt], bb[0], bb[2]);
                    mma_f16(acc[mt][2 * np + 1], a[mt], bb[1], bb[3]);
                }
            }
        }
    }
#pragma unroll
    for (int j = 0; j < 4; j++) {
        int o = n0 + j * 8 + 2 * q4;
        float b0 = tb[o], b1 = tb[o + 1];
#pragma unroll
        for (int mt = 0; mt < 2; mt++) {
            size_t r = (size_t)b * NQ_ + nbase + m0 + mt * 16 + g;
            *(uint32_t*)&d_theta[r * CI_ + o] = f2h2(acc[mt][j][0] + b0, acc[mt][j][1] + b1);
            *(uint32_t*)&d_theta[(r + 8) * CI_ + o] = f2h2(acc[mt][j][2] + b0, acc[mt][j][3] + b1);
        }
    }
}

// ---------------------------------------------------------------------------
// Kernel B: g/phi conv + maxpool fp16. 64n x 64o (o-split), 2 blocks/SM.
// smem halves: X0@0 X1@4608; G0@9216 G1@13824; P0@18432 P1@23040 ([64][72]).
// ---------------------------------------------------------------------------
__global__ void __launch_bounds__(256, 2) conv_gphi_kernel(
        const float* __restrict__ gb, const float* __restrict__ pb) {
    extern __shared__ unsigned short smh[];
    const int b = blockIdx.z;
    const int ob = blockIdx.y;
    const int t = blockIdx.x >> 4, hp = blockIdx.x & 15;
    const int nbase = t * 1024 + hp * 64;
    const int tid = threadIdx.x;
    const int warp = tid >> 5, lane = tid & 31;
    const int g = lane >> 2, q4 = lane & 3;
    const int m0 = (warp >> 2) * 32;
    const int n0 = (warp & 3) * 16;
    const uint32_t smb = (uint32_t)__cvta_generic_to_shared(smh);
    const uint32_t XB[2] = {0u, 4608u}, GB[2] = {9216u, 13824u}, PB[2] = {18432u, 23040u};
    const int fOff = FRAG_OFF(72);

    float ag[2][2][4], ap[2][2][4];
#pragma unroll
    for (int i = 0; i < 2; i++)
#pragma unroll
        for (int j = 0; j < 2; j++)
#pragma unroll
            for (int k = 0; k < 4; k++) { ag[i][j][k] = 0.f; ap[i][j][k] = 0.f; }

    const unsigned short* xb = d_xT + ((size_t)b * NQ_ + nbase) * C_;
    const unsigned short* gwb = gwr + (ob * 64) * C_;
    const unsigned short* pwb = pwr + (ob * 64) * C_;

#pragma unroll
    for (int u = 0; u < 2; u++) {
        int idx = u * 256 + tid;
        int r = idx >> 3, c8 = idx & 7;
        cpa(smb + (XB[0] + r * 72 + c8 * 8) * 2u, xb + (size_t)r * C_ + c8 * 8);
        cpa(smb + (GB[0] + r * 72 + c8 * 8) * 2u, gwb + r * C_ + c8 * 8);
        cpa(smb + (PB[0] + r * 72 + c8 * 8) * 2u, pwb + r * C_ + c8 * 8);
    }
    CP_COMMIT();

    for (int ch = 0; ch < 4; ch++) {
        CP_WAIT0();
        __syncthreads();
        if (ch < 3) {
            int c0 = (ch + 1) * 64, buf = (ch + 1) & 1;
#pragma unroll
            for (int u = 0; u < 2; u++) {
                int idx = u * 256 + tid;
                int r = idx >> 3, c8 = idx & 7;
                cpa(smb + (XB[buf] + r * 72 + c8 * 8) * 2u, xb + (size_t)r * C_ + c0 + c8 * 8);
                cpa(smb + (GB[buf] + r * 72 + c8 * 8) * 2u, gwb + r * C_ + c0 + c8 * 8);
                cpa(smb + (PB[buf] + r * 72 + c8 * 8) * 2u, pwb + r * C_ + c0 + c8 * 8);
            }
            CP_COMMIT();
        }
#pragma unroll
        for (int ks = 0; ks < 4; ks++) {
            uint32_t a[2][4];
#pragma unroll
            for (int mt = 0; mt < 2; mt++)
                ldsm_x4(a[mt], smb + (uint32_t)(XB[ch & 1] + (m0 + mt * 16) * 72
                                                + ks * 16 + fOff) * 2u);
            uint32_t bg_[4], bp_[4];
            ldsm_x4(bg_, smb + (uint32_t)(GB[ch & 1] + n0 * 72 + ks * 16 + fOff) * 2u);
            ldsm_x4(bp_, smb + (uint32_t)(PB[ch & 1] + n0 * 72 + ks * 16 + fOff) * 2u);
#pragma unroll
            for (int mt = 0; mt < 2; mt++) {
                mma_f16(ag[mt][0], a[mt], bg_[0], bg_[2]);
                mma_f16(ag[mt][1], a[mt], bg_[1], bg_[3]);
                mma_f16(ap[mt][0], a[mt], bp_[0], bp_[2]);
                mma_f16(ap[mt][1], a[mt], bp_[1], bp_[3]);
            }
        }
    }
    // stage fp32 S tiles, pool, write halves
    __syncthreads();
    float* Sg = (float*)smh;            // [64][68]
    float* Sp = (float*)smh + 4352;     // [64][68]
    float* Pv = (float*)smh + 8704;     // [64][20]
#pragma unroll
    for (int mt = 0; mt < 2; mt++) {
#pragma unroll
        for (int j = 0; j < 2; j++) {
            int r = m0 + mt * 16 + g;
            int o = n0 + j * 8 + 2 * q4;
            *(float2*)&Sg[r * 68 + o] = *(float2*)&ag[mt][j][0];
            *(float2*)&Sg[(r + 8) * 68 + o] = *(float2*)&ag[mt][j][2];
            *(float2*)&Sp[r * 68 + o] = *(float2*)&ap[mt][j][0];
            *(float2*)&Sp[(r + 8) * 68 + o] = *(float2*)&ap[mt][j][2];
        }
    }
    __syncthreads();
    const int mb = t * 256 + hp * 16;
    {
        int p = tid >> 4, o4 = (tid & 15) * 4;
        float4 bgv = *(const float4*)&gb[ob * 64 + o4];
        float4 bpv = *(const float4*)&pb[ob * 64 + o4];
        float4 r0, r1, r2, r3;
        r0 = *(float4*)&Sp[(2 * p) * 68 + o4];
        r1 = *(float4*)&Sp[(2 * p + 1) * 68 + o4];
        r2 = *(float4*)&Sp[(32 + 2 * p) * 68 + o4];
        r3 = *(float4*)&Sp[(33 + 2 * p) * 68 + o4];
        uint2 ko;
        ko.x = f2h2(fmaxf(fmaxf(r0.x, r1.x), fmaxf(r2.x, r3.x)) + bpv.x,
                    fmaxf(fmaxf(r0.y, r1.y), fmaxf(r2.y, r3.y)) + bpv.y);
        ko.y = f2h2(fmaxf(fmaxf(r0.z, r1.z), fmaxf(r2.z, r3.z)) + bpv.z,
                    fmaxf(fmaxf(r0.w, r1.w), fmaxf(r2.w, r3.w)) + bpv.w);
        *(uint2*)&d_key[((size_t)b * NKV_ + mb + p) * CI_ + ob * 64 + o4] = ko;
        r0 = *(float4*)&Sg[(2 * p) * 68 + o4];
        r1 = *(float4*)&Sg[(2 * p + 1) * 68 + o4];
        r2 = *(float4*)&Sg[(32 + 2 * p) * 68 + o4];
        r3 = *(float4*)&Sg[(33 + 2 * p) * 68 + o4];
        Pv[(o4 + 0) * 20 + p] = fmaxf(fmaxf(r0.x, r1.x), fmaxf(r2.x, r3.x)) + bgv.x;
        Pv[(o4 + 1) * 20 + p] = fmaxf(fmaxf(r0.y, r1.y), fmaxf(r2.y, r3.y)) + bgv.y;
        Pv[(o4 + 2) * 20 + p] = fmaxf(fmaxf(r0.z, r1.z), fmaxf(r2.z, r3.z)) + bgv.z;
        Pv[(o4 + 3) * 20 + p] = fmaxf(fmaxf(r0.w, r1.w), fmaxf(r2.w, r3.w)) + bgv.w;
    }
    __syncthreads();
    {
        int ci = tid >> 2, j = (tid & 3) * 4;
        uint2 v;
        v.x = f2h2(Pv[ci * 20 + j], Pv[ci * 20 + j + 1]);
        v.y = f2h2(Pv[ci * 20 + j + 2], Pv[ci * 20 + j + 3]);
        *(uint2*)&d_valT[((size_t)b * CI_ + ob * 64 + ci) * NKV_ + mb + j] = v;
    }
}

// ---------------------------------------------------------------------------
// Kernel C: fp16 flash attention, BQ=128, BK=64, online softmax, Q in regs.
// smem halves: K0@0 K1@8704 ([64][136]); V0@17408 V1@26624 ([128][72]);
//   Ps@35840 ([128][72]). total 45056 h = 90112 B. Q staged over K0+K1.
// ---------------------------------------------------------------------------
__global__ void __launch_bounds__(256, 1) attn_kernel() {
    extern __shared__ unsigned short smh[];
    const int b = blockIdx.y;
    const int qbase = blockIdx.x * 128;
    const int tid = threadIdx.x;
    const int warp = tid >> 5, lane = tid & 31;
    const int g = lane >> 2, q4 = lane & 3;
    const int r0 = warp * 16 + g;
    const uint32_t smb = (uint32_t)__cvta_generic_to_shared(smh);
    const uint32_t KB[2] = {0u, 8704u};
    const uint32_t VB[2] = {17408u, 26624u};
    const uint32_t PS = 35840u;

    const unsigned short* qb = d_theta + ((size_t)b * NQ_ + qbase) * CI_;
    const unsigned short* keyb = d_key + (size_t)b * NKV_ * CI_;
    const unsigned short* valb = d_valT + (size_t)b * CI_ * NKV_;

    // stage Q (over K region) + V0
#pragma unroll
    for (int u = 0; u < 8; u++) {
        int idx = u * 256 + tid;
        int r = idx >> 4, c8 = idx & 15;
        cpa(smb + (uint32_t)(r * 136 + c8 * 8) * 2u, qb + (size_t)r * CI_ + c8 * 8);
    }
#pragma unroll
    for (int u = 0; u < 4; u++) {
        int idx = u * 256 + tid;
        int r = idx >> 3, c8 = idx & 7;
        cpa(smb + (VB[0] + r * 72 + c8 * 8) * 2u, valb + (size_t)r * NKV_ + c8 * 8);
    }
    CP_COMMIT();
    CP_WAIT0();
    __syncthreads();

    uint32_t qfrag[8][4];
    {
        const uint32_t aQ = (uint32_t)((lane & 15) * 136 + (lane >> 4) * 8);
#pragma unroll
        for (int ks = 0; ks < 8; ks++)
            ldsm_x4(qfrag[ks], smb + (uint32_t)(warp * 16 * 136 + ks * 16 + aQ) * 2u);
    }
    __syncthreads();
    // K0
#pragma unroll
    for (int u = 0; u < 4; u++) {
        int idx = u * 256 + tid;
        int r = idx >> 4, c8 = idx & 15;
        cpa(smb + (KB[0] + r * 136 + c8 * 8) * 2u, keyb + (size_t)r * CI_ + c8 * 8);
    }
    CP_COMMIT();

    const int bK = FRAG_OFF(136);
    const int bV = FRAG_OFF(72);
    const int aP = warp * 16 * 72 + FRAG_OFF(72);

    float m[2] = {-3.0e38f, -3.0e38f}, l[2] = {0.f, 0.f};
    float oacc[16][4];
#pragma unroll
    for (int i = 0; i < 16; i++)
#pragma unroll
        for (int j = 0; j < 4; j++) oacc[i][j] = 0.f;

    for (int mt = 0; mt < NKV_ / 64; mt++) {
        CP_WAIT0();
        __syncthreads();
        if (mt + 1 < NKV_ / 64) {
            int nb = (mt + 1) * 64, buf = (mt + 1) & 1;
#pragma unroll
            for (int u = 0; u < 4; u++) {
                int idx = u * 256 + tid;
                int r = idx >> 4, c8 = idx & 15;
                cpa(smb + (KB[buf] + r * 136 + c8 * 8) * 2u,
                    keyb + (size_t)(nb + r) * CI_ + c8 * 8);
            }
#pragma unroll
            for (int u = 0; u < 4; u++) {
                int idx = u * 256 + tid;
                int r = idx >> 3, c8 = idx & 7;
                cpa(smb + (VB[buf] + r * 72 + c8 * 8) * 2u,
                    valb + (size_t)r * NKV_ + nb + c8 * 8);
            }
            CP_COMMIT();
        }

        // S = Q K^T : 8 ks(k16) x 4 n16-groups
        float sacc[8][4];
#pragma unroll
        for (int i = 0; i < 8; i++)
#pragma unroll
            for (int j = 0; j < 4; j++) sacc[i][j] = 0.f;
#pragma unroll
        for (int ks = 0; ks < 8; ks++) {
#pragma unroll
            for (int np = 0; np < 4; np++) {
                uint32_t bb[4];
                ldsm_x4(bb, smb + (uint32_t)(KB[mt & 1] + np * 16 * 136
                                             + ks * 16 + bK) * 2u);
                mma_f16(sacc[2 * np], qfrag[ks], bb[0], bb[2]);
                mma_f16(sacc[2 * np + 1], qfrag[ks], bb[1], bb[3]);
            }
        }

        // online softmax (rescale keeps P in [0,1] — fp16-safe)
#pragma unroll
        for (int h = 0; h < 2; h++) {
            float tmax = -3.0e38f;
#pragma unroll
            for (int nt = 0; nt < 8; nt++)
                tmax = fmaxf(tmax, fmaxf(sacc[nt][2 * h], sacc[nt][2 * h + 1]));
            tmax = fmaxf(tmax, __shfl_xor_sync(0xffffffffu, tmax, 1));
            tmax = fmaxf(tmax, __shfl_xor_sync(0xffffffffu, tmax, 2));
            float nm = fmaxf(m[h], tmax);
            float fac = __expf(m[h] - nm);
            float s = 0.f;
#pragma unroll
            for (int nt = 0; nt < 8; nt++) {
                float e0 = __expf(sacc[nt][2 * h] - nm);
                float e1 = __expf(sacc[nt][2 * h + 1] - nm);
                sacc[nt][2 * h] = e0; sacc[nt][2 * h + 1] = e1;
                s += e0 + e1;
            }
            s += __shfl_xor_sync(0xffffffffu, s, 1);
            s += __shfl_xor_sync(0xffffffffu, s, 2);
            l[h] = l[h] * fac + s;
            m[h] = nm;
#pragma unroll
            for (int ot = 0; ot < 16; ot++) {
                oacc[ot][2 * h]     *= fac;
                oacc[ot][2 * h + 1] *= fac;
            }
        }

        // P -> smem fp16 (own warp rows only)
#pragma unroll
        for (int nt = 0; nt < 8; nt++) {
            int cb = nt * 8 + 2 * q4;
            *(uint32_t*)&smh[PS + r0 * 72 + cb]       = f2h2(sacc[nt][0], sacc[nt][1]);
            *(uint32_t*)&smh[PS + (r0 + 8) * 72 + cb] = f2h2(sacc[nt][2], sacc[nt][3]);
        }
        __syncwarp();

        // O += P V : 4 ks(k16) x 8 n16-groups
#pragma unroll
        for (int ks = 0; ks < 4; ks++) {
            uint32_t a[4];
            ldsm_x4(a, smb + (uint32_t)(PS + ks * 16 + aP) * 2u);
#pragma unroll
            for (int np = 0; np < 8; np++) {
                uint32_t bb[4];
                ldsm_x4(bb, smb + (uint32_t)(VB[mt & 1] + np * 16 * 72
                                             + ks * 16 + bV) * 2u);
                mma_f16(oacc[2 * np], a, bb[0], bb[2]);
                mma_f16(oacc[2 * np + 1], a, bb[1], bb[3]);
            }
        }
    }

    float inv0 = 1.f / l[0], inv1 = 1.f / l[1];
    size_t row0 = (size_t)b * NQ_ + qbase + r0;
#pragma unroll
    for (int nt = 0; nt < 16; nt++) {
        int ci = nt * 8 + 2 * q4;
        *(uint32_t*)&d_yy[row0 * CI_ + ci] = f2h2(oacc[nt][0] * inv0, oacc[nt][1] * inv0);
        *(uint32_t*)&d_yy[(row0 + 8) * CI_ + ci] = f2h2(oacc[nt][2] * inv1, oacc[nt][3] * inv1);
    }
}

// ---------------------------------------------------------------------------
// Kernel D: wconv + BN + residual fp16. 128co x 64n, K=128 in 2 chunks.
// smem halves: W0@0 W1@9216 ([128][72]); Y0@18432 Y1@23040 ([64][72]). 55296 B.
// ---------------------------------------------------------------------------
__global__ void __launch_bounds__(256, 2) wconv_kernel(
        const float* __restrict__ x,
        const float* __restrict__ wb,
        const float* __restrict__ bng, const float* __restrict__ bnb,
        const float* __restrict__ bnm, const float* __restrict__ bnv,
        float* __restrict__ out) {
    extern __shared__ unsigned short smh[];
    const int b = blockIdx.z;
    const int cobase = blockIdx.y * 128;
    const int nbase = blockIdx.x * 64;
    const int tid = threadIdx.x;
    const int warp = tid >> 5, lane = tid & 31;
    const int g = lane >> 2, q4 = lane & 3;
    const int m0 = (warp >> 1) * 32;
    const int n0 = (warp & 1) * 32;
    const uint32_t smb = (uint32_t)__cvta_generic_to_shared(smh);
    const uint32_t WB[2] = {0u, 9216u}, YB[2] = {18432u, 23040u};
    const int fOff = FRAG_OFF(72);

    float acc[2][4][4];
#pragma unroll
    for (int i = 0; i < 2; i++)
#pragma unroll
        for (int j = 0; j < 4; j++)
#pragma unroll
            for (int k = 0; k < 4; k++) acc[i][j][k] = 0.f;

    const unsigned short* yb = d_yy + ((size_t)b * NQ_ + nbase) * CI_;

#pragma unroll
    for (int u = 0; u < 4; u++) {
        int idx = u * 256 + tid;
        int r = idx >> 3, c8 = idx & 7;
        cpa(smb + (WB[0] + r * 72 + c8 * 8) * 2u, &wwr[(cobase + r) * CI_ + c8 * 8]);
    }
#pragma unroll
    for (int u = 0; u < 2; u++) {
        int idx = u * 256 + tid;
        int r = idx >> 3, c8 = idx & 7;
        cpa(smb + (YB[0] + r * 72 + c8 * 8) * 2u, yb + (size_t)r * CI_ + c8 * 8);
    }
    CP_COMMIT();

    for (int ch = 0; ch < 2; ch++) {
        CP_WAIT0();
        __syncthreads();
        if (ch < 1) {
#pragma unroll
            for (int u = 0; u < 4; u++) {
                int idx = u * 256 + tid;
                int r = idx >> 3, c8 = idx & 7;
                cpa(smb + (WB[1] + r * 72 + c8 * 8) * 2u,
                    &wwr[(cobase + r) * CI_ + 64 + c8 * 8]);
            }
#pragma unroll
            for (int u = 0; u < 2; u++) {
                int idx = u * 256 + tid;
                int r = idx >> 3, c8 = idx & 7;
                cpa(smb + (YB[1] + r * 72 + c8 * 8) * 2u,
                    yb + (size_t)r * CI_ + 64 + c8 * 8);
            }
            CP_COMMIT();
        }
#pragma unroll
        for (int ks = 0; ks < 4; ks++) {
            uint32_t a[2][4];
#pragma unroll
            for (int mt = 0; mt < 2; mt++)
                ldsm_x4(a[mt], smb + (uint32_t)(WB[ch & 1] + (m0 + mt * 16) * 72
                                                + ks * 16 + fOff) * 2u);
#pragma unroll
            for (int np = 0; np < 2; np++) {
                uint32_t bb[4];
                ldsm_x4(bb, smb + (uint32_t)(YB[ch & 1] + (n0 + np * 16) * 72
                                             + ks * 16 + fOff) * 2u);
#pragma unroll
                for (int mt = 0; mt < 2; mt++) {
                    mma_f16(acc[mt][2 * np], a[mt], bb[0], bb[2]);
                    mma_f16(acc[mt][2 * np + 1], a[mt], bb[1], bb[3]);
                }
            }
        }
    }

    float sc[2][2], sh[2][2];
#pragma unroll
    for (int mt = 0; mt < 2; mt++)
#pragma unroll
        for (int h = 0; h < 2; h++) {
            int co = cobase + m0 + mt * 16 + g + h * 8;
            float s = bng[co] * rsqrtf(bnv[co] + 1e-5f);
            sc[mt][h] = s;
            sh[mt][h] = bnb[co] - bnm[co] * s + s * wb[co];
        }
#pragma unroll
    for (int mt = 0; mt < 2; mt++) {
#pragma unroll
        for (int j = 0; j < 4; j++) {
            int n = nbase + n0 + j * 8 + 2 * q4;
#pragma unroll
            for (int h = 0; h < 2; h++) {
                int co = cobase + m0 + mt * 16 + g + h * 8;
                size_t base = ((size_t)b * C_ + co) * NQ_ + n;
                float2 xv = *(const float2*)&x[base];
                float2 o;
                o.x = acc[mt][j][2 * h]     * sc[mt][h] + sh[mt][h] + xv.x;
                o.y = acc[mt][j][2 * h + 1] * sc[mt][h] + sh[mt][h] + xv.y;
                *(float2*)&out[base] = o;
            }
        }
    }
}

// ---------------------------------------------------------------------------
extern "C" void kernel_launch(void* const* d_in, const int* in_sizes, int n_in,
                              void* d_out, int out_size) {
    const float* x    = (const float*)d_in[0];
    const float* g_w  = (const float*)d_in[1];
    const float* g_b  = (const float*)d_in[2];
    const float* th_w = (const float*)d_in[3];
    const float* th_b = (const float*)d_in[4];
    const float* ph_w = (const float*)d_in[5];
    const float* ph_b = (const float*)d_in[6];
    const float* w_w  = (const float*)d_in[7];
    const float* w_b  = (const float*)d_in[8];
    const float* bn_g = (const float*)d_in[9];
    const float* bn_b = (const float*)d_in[10];
    const float* bn_m = (const float*)d_in[11];
    const float* bn_v = (const float*)d_in[12];
    float* out = (float*)d_out;

    const int smA = 27648 * 2;   // 55296
    const int smB = 27648 * 2;   // 55296
    const int smC = 45056 * 2;   // 90112
    const int smD = 27648 * 2;   // 55296

    cudaFuncSetAttribute(conv_theta_kernel, cudaFuncAttributeMaxDynamicSharedMemorySize, smA);
    cudaFuncSetAttribute(conv_gphi_kernel,  cudaFuncAttributeMaxDynamicSharedMemorySize, smB);
    cudaFuncSetAttribute(attn_kernel,       cudaFuncAttributeMaxDynamicSharedMemorySize, smC);
    cudaFuncSetAttribute(wconv_kernel,      cudaFuncAttributeMaxDynamicSharedMemorySize, smD);

    prep_kernel<<<dim3(128, 4, 5), 256>>>(x, th_w, g_w, ph_w, w_w);
    conv_theta_kernel<<<dim3(NQ_ / 64, B_), 256, smA>>>(th_b);
    conv_gphi_kernel<<<dim3(128, 2, B_), 256, smB>>>(g_b, ph_b);
    attn_kernel<<<dim3(NQ_ / 128, B_), 256, smC>>>();
    wconv_kernel<<<dim3(NQ_ / 64, 2, B_), 256, smD>>>(x, w_b,
                                                      bn_g, bn_b, bn_m, bn_v, out);
}

// round 13
// speedup vs baseline: 1.9528x; 1.0307x over previous
#include <cuda_runtime.h>
#include <cuda_fp16.h>
#include <math.h>
#include <stdint.h>

#define B_  4
#define C_  256
#define CI_ 128
#define NQ_ 8192
#define NKV_ 2048
#define LOG2E 1.44269504f

// scratch (no cudaMalloc allowed) — all fp16 payloads stored as u16
__device__ unsigned short d_xT  [(size_t)B_ * NQ_ * C_];   // (b, n, c)
__device__ unsigned short twr   [CI_ * C_];
__device__ unsigned short gwr   [CI_ * C_];
__device__ unsigned short pwr   [CI_ * C_];
__device__ unsigned short wwr   [C_ * CI_];
__device__ unsigned short d_theta[(size_t)B_ * NQ_ * CI_]; // (b, n, ci) pre-scaled by log2e
__device__ unsigned short d_key  [(size_t)B_ * NKV_ * CI_];// (b, m, ci)
__device__ unsigned short d_valT [(size_t)B_ * CI_ * NKV_];// (b, ci, m)
__device__ unsigned short d_yy   [(size_t)B_ * NQ_ * CI_]; // (b, n, ci)

__device__ __forceinline__ uint32_t f2h2(float lo, float hi) {
    uint32_t r;
    asm("cvt.rn.f16x2.f32 %0, %1, %2;" : "=r"(r) : "f"(hi), "f"(lo));
    return r;
}

__device__ __forceinline__ void mma_f16(float* c, const uint32_t* a,
                                        uint32_t b0, uint32_t b1) {
    asm volatile(
        "mma.sync.aligned.m16n8k16.row.col.f32.f16.f16.f32 "
        "{%0,%1,%2,%3}, {%4,%5,%6,%7}, {%8,%9}, {%0,%1,%2,%3};"
        : "+f"(c[0]), "+f"(c[1]), "+f"(c[2]), "+f"(c[3])
        : "r"(a[0]), "r"(a[1]), "r"(a[2]), "r"(a[3]), "r"(b0), "r"(b1));
}

__device__ __forceinline__ void ldsm_x4(uint32_t* r, uint32_t a) {
    asm volatile("ldmatrix.sync.aligned.m8n8.x4.shared.b16 {%0,%1,%2,%3}, [%4];"
                 : "=r"(r[0]), "=r"(r[1]), "=r"(r[2]), "=r"(r[3]) : "r"(a));
}

__device__ __forceinline__ void cpa(uint32_t dst, const void* src) {
    asm volatile("cp.async.cg.shared.global [%0], [%1], 16;" :: "r"(dst), "l"(src));
}
#define CP_COMMIT() asm volatile("cp.async.commit_group;")
#define CP_WAIT0()  asm volatile("cp.async.wait_group 0;")

// fragment base offsets (in halves): row = lane&15, k-half = lane>>4
#define FRAG_OFF(stride) ((lane & 15) * (stride) + (lane >> 4) * 8)

// ---------------------------------------------------------------------------
// Prep: z<4 -> transpose+round x slice to fp16; z==4 -> round weights.
// grid (128, 4, 5), 256 threads.
// ---------------------------------------------------------------------------
__global__ void __launch_bounds__(256) prep_kernel(
        const float* __restrict__ x,
        const float* __restrict__ tw, const float* __restrict__ gw,
        const float* __restrict__ pw, const float* __restrict__ ww) {
    if (blockIdx.z == 4) {
        int bid = blockIdx.y * 128 + blockIdx.x;
        if (bid >= 16) return;
        int i = (bid * 256 + threadIdx.x) * 8;
        float4 v0, v1;
        uint2 o;
        v0 = *(const float4*)&tw[i]; v1 = *(const float4*)&tw[i + 4];
        o.x = f2h2(v0.x, v0.y); o.y = f2h2(v0.z, v0.w);
        *(uint2*)&twr[i] = o;
        o.x = f2h2(v1.x, v1.y); o.y = f2h2(v1.z, v1.w);
        *(uint2*)&twr[i + 4] = o;
        v0 = *(const float4*)&gw[i]; v1 = *(const float4*)&gw[i + 4];
        o.x = f2h2(v0.x, v0.y); o.y = f2h2(v0.z, v0.w);
        *(uint2*)&gwr[i] = o;
        o.x = f2h2(v1.x, v1.y); o.y = f2h2(v1.z, v1.w);
        *(uint2*)&gwr[i + 4] = o;
        v0 = *(const float4*)&pw[i]; v1 = *(const float4*)&pw[i + 4];
        o.x = f2h2(v0.x, v0.y); o.y = f2h2(v0.z, v0.w);
        *(uint2*)&pwr[i] = o;
        o.x = f2h2(v1.x, v1.y); o.y = f2h2(v1.z, v1.w);
        *(uint2*)&pwr[i + 4] = o;
        v0 = *(const float4*)&ww[i]; v1 = *(const float4*)&ww[i + 4];
        o.x = f2h2(v0.x, v0.y); o.y = f2h2(v0.z, v0.w);
        *(uint2*)&wwr[i] = o;
        o.x = f2h2(v1.x, v1.y); o.y = f2h2(v1.z, v1.w);
        *(uint2*)&wwr[i + 4] = o;
        return;
    }
    __shared__ float Ts[64 * 65];
    const int b = blockIdx.z, cb = blockIdx.y * 64, nb = blockIdx.x * 64;
    const int tid = threadIdx.x;
#pragma unroll
    for (int u = 0; u < 4; u++) {
        int idx = u * 256 + tid;
        int cc = idx >> 4, j4 = idx & 15;
        float4 v = *(const float4*)&x[((size_t)b * C_ + cb + cc) * NQ_ + nb + j4 * 4];
        Ts[(j4 * 4 + 0) * 65 + cc] = v.x;
        Ts[(j4 * 4 + 1) * 65 + cc] = v.y;
        Ts[(j4 * 4 + 2) * 65 + cc] = v.z;
        Ts[(j4 * 4 + 3) * 65 + cc] = v.w;
    }
    __syncthreads();
#pragma unroll
    for (int u = 0; u < 4; u++) {
        int idx = u * 256 + tid;
        int nn = idx >> 4, c4 = idx & 15;
        uint2 o;
        o.x = f2h2(Ts[nn * 65 + c4 * 4], Ts[nn * 65 + c4 * 4 + 1]);
        o.y = f2h2(Ts[nn * 65 + c4 * 4 + 2], Ts[nn * 65 + c4 * 4 + 3]);
        *(uint2*)&d_xT[((size_t)b * NQ_ + nb + nn) * C_ + cb + c4 * 4] = o;
    }
}

// ---------------------------------------------------------------------------
// Kernel A: theta conv fp16. 64n x 128o, K=256 in 4 chunks, 2 blocks/SM.
// Epilogue scales by LOG2E (d_theta feeds only attention's exp2-softmax).
// ---------------------------------------------------------------------------
__global__ void __launch_bounds__(256, 2) conv_theta_kernel(const float* __restrict__ tb) {
    extern __shared__ unsigned short smh[];
    const int b = blockIdx.y;
    const int nbase = blockIdx.x * 64;
    const int tid = threadIdx.x;
    const int warp = tid >> 5, lane = tid & 31;
    const int g = lane >> 2, q4 = lane & 3;
    const int m0 = (warp >> 2) * 32;
    const int n0 = (warp & 3) * 32;
    const uint32_t smb = (uint32_t)__cvta_generic_to_shared(smh);
    const uint32_t XB[2] = {0u, 4608u}, WB[2] = {9216u, 18432u};
    const int fOff = FRAG_OFF(72);

    float acc[2][4][4];
#pragma unroll
    for (int i = 0; i < 2; i++)
#pragma unroll
        for (int j = 0; j < 4; j++)
#pragma unroll
            for (int k = 0; k < 4; k++) acc[i][j][k] = 0.f;

    const unsigned short* xb = d_xT + ((size_t)b * NQ_ + nbase) * C_;

#pragma unroll
    for (int u = 0; u < 2; u++) {
        int idx = u * 256 + tid;
        int r = idx >> 3, c8 = idx & 7;
        cpa(smb + (XB[0] + r * 72 + c8 * 8) * 2u, xb + (size_t)r * C_ + c8 * 8);
    }
#pragma unroll
    for (int u = 0; u < 4; u++) {
        int idx = u * 256 + tid;
        int r = idx >> 3, c8 = idx & 7;
        cpa(smb + (WB[0] + r * 72 + c8 * 8) * 2u, &twr[r * C_ + c8 * 8]);
    }
    CP_COMMIT();

    for (int ch = 0; ch < 4; ch++) {
        CP_WAIT0();
        __syncthreads();
        if (ch < 3) {
            int c0 = (ch + 1) * 64, buf = (ch + 1) & 1;
#pragma unroll
            for (int u = 0; u < 2; u++) {
                int idx = u * 256 + tid;
                int r = idx >> 3, c8 = idx & 7;
                cpa(smb + (XB[buf] + r * 72 + c8 * 8) * 2u, xb + (size_t)r * C_ + c0 + c8 * 8);
            }
#pragma unroll
            for (int u = 0; u < 4; u++) {
                int idx = u * 256 + tid;
                int r = idx >> 3, c8 = idx & 7;
                cpa(smb + (WB[buf] + r * 72 + c8 * 8) * 2u, &twr[r * C_ + c0 + c8 * 8]);
            }
            CP_COMMIT();
        }
#pragma unroll
        for (int ks = 0; ks < 4; ks++) {
            uint32_t a[2][4];
#pragma unroll
            for (int mt = 0; mt < 2; mt++)
                ldsm_x4(a[mt], smb + (uint32_t)(XB[ch & 1] + (m0 + mt * 16) * 72
                                                + ks * 16 + fOff) * 2u);
#pragma unroll
            for (int np = 0; np < 2; np++) {
                uint32_t bb[4];
                ldsm_x4(bb, smb + (uint32_t)(WB[ch & 1] + (n0 + np * 16) * 72
                                             + ks * 16 + fOff) * 2u);
#pragma unroll
                for (int mt = 0; mt < 2; mt++) {
                    mma_f16(acc[mt][2 * np], a[mt], bb[0], bb[2]);
                    mma_f16(acc[mt][2 * np + 1], a[mt], bb[1], bb[3]);
                }
            }
        }
    }
#pragma unroll
    for (int j = 0; j < 4; j++) {
        int o = n0 + j * 8 + 2 * q4;
        float b0 = tb[o], b1 = tb[o + 1];
#pragma unroll
        for (int mt = 0; mt < 2; mt++) {
            size_t r = (size_t)b * NQ_ + nbase + m0 + mt * 16 + g;
            *(uint32_t*)&d_theta[r * CI_ + o] =
                f2h2((acc[mt][j][0] + b0) * LOG2E, (acc[mt][j][1] + b1) * LOG2E);
            *(uint32_t*)&d_theta[(r + 8) * CI_ + o] =
                f2h2((acc[mt][j][2] + b0) * LOG2E, (acc[mt][j][3] + b1) * LOG2E);
        }
    }
}

// ---------------------------------------------------------------------------
// Kernel B: g/phi conv + maxpool fp16. 64n x 64o (o-split), 2 blocks/SM.
// ---------------------------------------------------------------------------
__global__ void __launch_bounds__(256, 2) conv_gphi_kernel(
        const float* __restrict__ gb, const float* __restrict__ pb) {
    extern __shared__ unsigned short smh[];
    const int b = blockIdx.z;
    const int ob = blockIdx.y;
    const int t = blockIdx.x >> 4, hp = blockIdx.x & 15;
    const int nbase = t * 1024 + hp * 64;
    const int tid = threadIdx.x;
    const int warp = tid >> 5, lane = tid & 31;
    const int g = lane >> 2, q4 = lane & 3;
    const int m0 = (warp >> 2) * 32;
    const int n0 = (warp & 3) * 16;
    const uint32_t smb = (uint32_t)__cvta_generic_to_shared(smh);
    const uint32_t XB[2] = {0u, 4608u}, GB[2] = {9216u, 13824u}, PB[2] = {18432u, 23040u};
    const int fOff = FRAG_OFF(72);

    float ag[2][2][4], ap[2][2][4];
#pragma unroll
    for (int i = 0; i < 2; i++)
#pragma unroll
        for (int j = 0; j < 2; j++)
#pragma unroll
            for (int k = 0; k < 4; k++) { ag[i][j][k] = 0.f; ap[i][j][k] = 0.f; }

    const unsigned short* xb = d_xT + ((size_t)b * NQ_ + nbase) * C_;
    const unsigned short* gwb = gwr + (ob * 64) * C_;
    const unsigned short* pwb = pwr + (ob * 64) * C_;

#pragma unroll
    for (int u = 0; u < 2; u++) {
        int idx = u * 256 + tid;
        int r = idx >> 3, c8 = idx & 7;
        cpa(smb + (XB[0] + r * 72 + c8 * 8) * 2u, xb + (size_t)r * C_ + c8 * 8);
        cpa(smb + (GB[0] + r * 72 + c8 * 8) * 2u, gwb + r * C_ + c8 * 8);
        cpa(smb + (PB[0] + r * 72 + c8 * 8) * 2u, pwb + r * C_ + c8 * 8);
    }
    CP_COMMIT();

    for (int ch = 0; ch < 4; ch++) {
        CP_WAIT0();
        __syncthreads();
        if (ch < 3) {
            int c0 = (ch + 1) * 64, buf = (ch + 1) & 1;
#pragma unroll
            for (int u = 0; u < 2; u++) {
                int idx = u * 256 + tid;
                int r = idx >> 3, c8 = idx & 7;
                cpa(smb + (XB[buf] + r * 72 + c8 * 8) * 2u, xb + (size_t)r * C_ + c0 + c8 * 8);
                cpa(smb + (GB[buf] + r * 72 + c8 * 8) * 2u, gwb + r * C_ + c0 + c8 * 8);
                cpa(smb + (PB[buf] + r * 72 + c8 * 8) * 2u, pwb + r * C_ + c0 + c8 * 8);
            }
            CP_COMMIT();
        }
#pragma unroll
        for (int ks = 0; ks < 4; ks++) {
            uint32_t a[2][4];
#pragma unroll
            for (int mt = 0; mt < 2; mt++)
                ldsm_x4(a[mt], smb + (uint32_t)(XB[ch & 1] + (m0 + mt * 16) * 72
                                                + ks * 16 + fOff) * 2u);
            uint32_t bg_[4], bp_[4];
            ldsm_x4(bg_, smb + (uint32_t)(GB[ch & 1] + n0 * 72 + ks * 16 + fOff) * 2u);
            ldsm_x4(bp_, smb + (uint32_t)(PB[ch & 1] + n0 * 72 + ks * 16 + fOff) * 2u);
#pragma unroll
            for (int mt = 0; mt < 2; mt++) {
                mma_f16(ag[mt][0], a[mt], bg_[0], bg_[2]);
                mma_f16(ag[mt][1], a[mt], bg_[1], bg_[3]);
                mma_f16(ap[mt][0], a[mt], bp_[0], bp_[2]);
                mma_f16(ap[mt][1], a[mt], bp_[1], bp_[3]);
            }
        }
    }
    __syncthreads();
    float* Sg = (float*)smh;            // [64][68]
    float* Sp = (float*)smh + 4352;     // [64][68]
    float* Pv = (float*)smh + 8704;     // [64][20]
#pragma unroll
    for (int mt = 0; mt < 2; mt++) {
#pragma unroll
        for (int j = 0; j < 2; j++) {
            int r = m0 + mt * 16 + g;
            int o = n0 + j * 8 + 2 * q4;
            *(float2*)&Sg[r * 68 + o] = *(float2*)&ag[mt][j][0];
            *(float2*)&Sg[(r + 8) * 68 + o] = *(float2*)&ag[mt][j][2];
            *(float2*)&Sp[r * 68 + o] = *(float2*)&ap[mt][j][0];
            *(float2*)&Sp[(r + 8) * 68 + o] = *(float2*)&ap[mt][j][2];
        }
    }
    __syncthreads();
    const int mb = t * 256 + hp * 16;
    {
        int p = tid >> 4, o4 = (tid & 15) * 4;
        float4 bgv = *(const float4*)&gb[ob * 64 + o4];
        float4 bpv = *(const float4*)&pb[ob * 64 + o4];
        float4 r0, r1, r2, r3;
        r0 = *(float4*)&Sp[(2 * p) * 68 + o4];
        r1 = *(float4*)&Sp[(2 * p + 1) * 68 + o4];
        r2 = *(float4*)&Sp[(32 + 2 * p) * 68 + o4];
        r3 = *(float4*)&Sp[(33 + 2 * p) * 68 + o4];
        uint2 ko;
        ko.x = f2h2(fmaxf(fmaxf(r0.x, r1.x), fmaxf(r2.x, r3.x)) + bpv.x,
                    fmaxf(fmaxf(r0.y, r1.y), fmaxf(r2.y, r3.y)) + bpv.y);
        ko.y = f2h2(fmaxf(fmaxf(r0.z, r1.z), fmaxf(r2.z, r3.z)) + bpv.z,
                    fmaxf(fmaxf(r0.w, r1.w), fmaxf(r2.w, r3.w)) + bpv.w);
        *(uint2*)&d_key[((size_t)b * NKV_ + mb + p) * CI_ + ob * 64 + o4] = ko;
        r0 = *(float4*)&Sg[(2 * p) * 68 + o4];
        r1 = *(float4*)&Sg[(2 * p + 1) * 68 + o4];
        r2 = *(float4*)&Sg[(32 + 2 * p) * 68 + o4];
        r3 = *(float4*)&Sg[(33 + 2 * p) * 68 + o4];
        Pv[(o4 + 0) * 20 + p] = fmaxf(fmaxf(r0.x, r1.x), fmaxf(r2.x, r3.x)) + bgv.x;
        Pv[(o4 + 1) * 20 + p] = fmaxf(fmaxf(r0.y, r1.y), fmaxf(r2.y, r3.y)) + bgv.y;
        Pv[(o4 + 2) * 20 + p] = fmaxf(fmaxf(r0.z, r1.z), fmaxf(r2.z, r3.z)) + bgv.z;
        Pv[(o4 + 3) * 20 + p] = fmaxf(fmaxf(r0.w, r1.w), fmaxf(r2.w, r3.w)) + bgv.w;
    }
    __syncthreads();
    {
        int ci = tid >> 2, j = (tid & 3) * 4;
        uint2 v;
        v.x = f2h2(Pv[ci * 20 + j], Pv[ci * 20 + j + 1]);
        v.y = f2h2(Pv[ci * 20 + j + 2], Pv[ci * 20 + j + 3]);
        *(uint2*)&d_valT[((size_t)b * CI_ + ob * 64 + ci) * NKV_ + mb + j] = v;
    }
}

// ---------------------------------------------------------------------------
// Kernel C: fp16 flash attention. BQ=128, BK=64. Online softmax (exp2 units,
// conditional rescale), P kept in registers (S-accum -> PV A-frag directly).
// smem halves: K0@0 K1@8704 ([64][136]); V0@17408 V1@26624 ([128][72]).
// Q staged over K0+K1 ([128][136] = 17408 halves, exact fit).
// ---------------------------------------------------------------------------
__global__ void __launch_bounds__(256, 1) attn_kernel() {
    extern __shared__ unsigned short smh[];
    const int b = blockIdx.y;
    const int qbase = blockIdx.x * 128;
    const int tid = threadIdx.x;
    const int warp = tid >> 5, lane = tid & 31;
    const int g = lane >> 2, q4 = lane & 3;
    const int r0 = warp * 16 + g;
    const uint32_t smb = (uint32_t)__cvta_generic_to_shared(smh);
    const uint32_t KB[2] = {0u, 8704u};
    const uint32_t VB[2] = {17408u, 26624u};

    const unsigned short* qb = d_theta + ((size_t)b * NQ_ + qbase) * CI_;
    const unsigned short* keyb = d_key + (size_t)b * NKV_ * CI_;
    const unsigned short* valb = d_valT + (size_t)b * CI_ * NKV_;

    // stage Q (over K region) + V0
#pragma unroll
    for (int u = 0; u < 8; u++) {
        int idx = u * 256 + tid;
        int r = idx >> 4, c8 = idx & 15;
        cpa(smb + (uint32_t)(r * 136 + c8 * 8) * 2u, qb + (size_t)r * CI_ + c8 * 8);
    }
#pragma unroll
    for (int u = 0; u < 4; u++) {
        int idx = u * 256 + tid;
        int r = idx >> 3, c8 = idx & 7;
        cpa(smb + (VB[0] + r * 72 + c8 * 8) * 2u, valb + (size_t)r * NKV_ + c8 * 8);
    }
    CP_COMMIT();
    CP_WAIT0();
    __syncthreads();

    uint32_t qfrag[8][4];
    {
        const uint32_t aQ = (uint32_t)((lane & 15) * 136 + (lane >> 4) * 8);
#pragma unroll
        for (int ks = 0; ks < 8; ks++)
            ldsm_x4(qfrag[ks], smb + (uint32_t)(warp * 16 * 136 + ks * 16 + aQ) * 2u);
    }
    __syncthreads();
    // K0
#pragma unroll
    for (int u = 0; u < 4; u++) {
        int idx = u * 256 + tid;
        int r = idx >> 4, c8 = idx & 15;
        cpa(smb + (KB[0] + r * 136 + c8 * 8) * 2u, keyb + (size_t)r * CI_ + c8 * 8);
    }
    CP_COMMIT();

    const int bK = FRAG_OFF(136);
    const int bV = FRAG_OFF(72);

    float m[2] = {-3.0e38f, -3.0e38f}, l[2] = {0.f, 0.f};
    float oacc[16][4];
#pragma unroll
    for (int i = 0; i < 16; i++)
#pragma unroll
        for (int j = 0; j < 4; j++) oacc[i][j] = 0.f;

    for (int mt = 0; mt < NKV_ / 64; mt++) {
        CP_WAIT0();
        __syncthreads();
        if (mt + 1 < NKV_ / 64) {
            int nb = (mt + 1) * 64, buf = (mt + 1) & 1;
#pragma unroll
            for (int u = 0; u < 4; u++) {
                int idx = u * 256 + tid;
                int r = idx >> 4, c8 = idx & 15;
                cpa(smb + (KB[buf] + r * 136 + c8 * 8) * 2u,
                    keyb + (size_t)(nb + r) * CI_ + c8 * 8);
            }
#pragma unroll
            for (int u = 0; u < 4; u++) {
                int idx = u * 256 + tid;
                int r = idx >> 3, c8 = idx & 7;
                cpa(smb + (VB[buf] + r * 72 + c8 * 8) * 2u,
                    valb + (size_t)r * NKV_ + nb + c8 * 8);
            }
            CP_COMMIT();
        }

        // S = Q K^T (log2 units): 8 ks(k16) x 4 n16-groups
        float sacc[8][4];
#pragma unroll
        for (int i = 0; i < 8; i++)
#pragma unroll
            for (int j = 0; j < 4; j++) sacc[i][j] = 0.f;
#pragma unroll
        for (int ks = 0; ks < 8; ks++) {
#pragma unroll
            for (int np = 0; np < 4; np++) {
                uint32_t bb[4];
                ldsm_x4(bb, smb + (uint32_t)(KB[mt & 1] + np * 16 * 136
                                             + ks * 16 + bK) * 2u);
                mma_f16(sacc[2 * np], qfrag[ks], bb[0], bb[2]);
                mma_f16(sacc[2 * np + 1], qfrag[ks], bb[1], bb[3]);
            }
        }

        // online softmax in exp2 units; rescale only when row max rises
#pragma unroll
        for (int h = 0; h < 2; h++) {
            float tmax = -3.0e38f;
#pragma unroll
            for (int nt = 0; nt < 8; nt++)
                tmax = fmaxf(tmax, fmaxf(sacc[nt][2 * h], sacc[nt][2 * h + 1]));
            tmax = fmaxf(tmax, __shfl_xor_sync(0xffffffffu, tmax, 1));
            tmax = fmaxf(tmax, __shfl_xor_sync(0xffffffffu, tmax, 2));
            if (tmax > m[h]) {
                float fac = exp2f(m[h] - tmax);
                m[h] = tmax;
                l[h] *= fac;
#pragma unroll
                for (int ot = 0; ot < 16; ot++) {
                    oacc[ot][2 * h]     *= fac;
                    oacc[ot][2 * h + 1] *= fac;
                }
            }
        }

        // exp2 into P (registers), accumulate l (lane-local; reduce at end)
#pragma unroll
        for (int nt = 0; nt < 8; nt++) {
            float e0 = exp2f(sacc[nt][0] - m[0]);
            float e1 = exp2f(sacc[nt][1] - m[0]);
            float e2 = exp2f(sacc[nt][2] - m[1]);
            float e3 = exp2f(sacc[nt][3] - m[1]);
            l[0] += e0 + e1;
            l[1] += e2 + e3;
            sacc[nt][0] = e0; sacc[nt][1] = e1;
            sacc[nt][2] = e2; sacc[nt][3] = e3;
        }

        // O += P V : P fragments straight from registers
#pragma unroll
        for (int ks = 0; ks < 4; ks++) {
            uint32_t a[4];
            a[0] = f2h2(sacc[2 * ks][0], sacc[2 * ks][1]);
            a[1] = f2h2(sacc[2 * ks][2], sacc[2 * ks][3]);
            a[2] = f2h2(sacc[2 * ks + 1][0], sacc[2 * ks + 1][1]);
            a[3] = f2h2(sacc[2 * ks + 1][2], sacc[2 * ks + 1][3]);
#pragma unroll
            for (int np = 0; np < 8; np++) {
                uint32_t bb[4];
                ldsm_x4(bb, smb + (uint32_t)(VB[mt & 1] + np * 16 * 72
                                             + ks * 16 + bV) * 2u);
                mma_f16(oacc[2 * np], a, bb[0], bb[2]);
                mma_f16(oacc[2 * np + 1], a, bb[1], bb[3]);
            }
        }
    }

    // deferred l lane-reduction, normalize, write
#pragma unroll
    for (int h = 0; h < 2; h++) {
        l[h] += __shfl_xor_sync(0xffffffffu, l[h], 1);
        l[h] += __shfl_xor_sync(0xffffffffu, l[h], 2);
    }
    float inv0 = 1.f / l[0], inv1 = 1.f / l[1];
    size_t row0 = (size_t)b * NQ_ + qbase + r0;
#pragma unroll
    for (int nt = 0; nt < 16; nt++) {
        int ci = nt * 8 + 2 * q4;
        *(uint32_t*)&d_yy[row0 * CI_ + ci] = f2h2(oacc[nt][0] * inv0, oacc[nt][1] * inv0);
        *(uint32_t*)&d_yy[(row0 + 8) * CI_ + ci] = f2h2(oacc[nt][2] * inv1, oacc[nt][3] * inv1);
    }
}

// ---------------------------------------------------------------------------
// Kernel D: wconv + BN + residual fp16. 128co x 64n, K=128 in 2 chunks.
// ---------------------------------------------------------------------------
__global__ void __launch_bounds__(256, 2) wconv_kernel(
        const float* __restrict__ x,
        const float* __restrict__ wb,
        const float* __restrict__ bng, const float* __restrict__ bnb,
        const float* __restrict__ bnm, const float* __restrict__ bnv,
        float* __restrict__ out) {
    extern __shared__ unsigned short smh[];
    const int b = blockIdx.z;
    const int cobase = blockIdx.y * 128;
    const int nbase = blockIdx.x * 64;
    const int tid = threadIdx.x;
    const int warp = tid >> 5, lane = tid & 31;
    const int g = lane >> 2, q4 = lane & 3;
    const int m0 = (warp >> 1) * 32;
    const int n0 = (warp & 1) * 32;
    const uint32_t smb = (uint32_t)__cvta_generic_to_shared(smh);
    const uint32_t WB[2] = {0u, 9216u}, YB[2] = {18432u, 23040u};
    const int fOff = FRAG_OFF(72);

    float acc[2][4][4];
#pragma unroll
    for (int i = 0; i < 2; i++)
#pragma unroll
        for (int j = 0; j < 4; j++)
#pragma unroll
            for (int k = 0; k < 4; k++) acc[i][j][k] = 0.f;

    const unsigned short* yb = d_yy + ((size_t)b * NQ_ + nbase) * CI_;

#pragma unroll
    for (int u = 0; u < 4; u++) {
        int idx = u * 256 + tid;
        int r = idx >> 3, c8 = idx & 7;
        cpa(smb + (WB[0] + r * 72 + c8 * 8) * 2u, &wwr[(cobase + r) * CI_ + c8 * 8]);
    }
#pragma unroll
    for (int u = 0; u < 2; u++) {
        int idx = u * 256 + tid;
        int r = idx >> 3, c8 = idx & 7;
        cpa(smb + (YB[0] + r * 72 + c8 * 8) * 2u, yb + (size_t)r * CI_ + c8 * 8);
    }
    CP_COMMIT();

    for (int ch = 0; ch < 2; ch++) {
        CP_WAIT0();
        __syncthreads();
        if (ch < 1) {
#pragma unroll
            for (int u = 0; u < 4; u++) {
                int idx = u * 256 + tid;
                int r = idx >> 3, c8 = idx & 7;
                cpa(smb + (WB[1] + r * 72 + c8 * 8) * 2u,
                    &wwr[(cobase + r) * CI_ + 64 + c8 * 8]);
            }
#pragma unroll
            for (int u = 0; u < 2; u++) {
                int idx = u * 256 + tid;
                int r = idx >> 3, c8 = idx & 7;
                cpa(smb + (YB[1] + r * 72 + c8 * 8) * 2u,
                    yb + (size_t)r * CI_ + 64 + c8 * 8);
            }
            CP_COMMIT();
        }
#pragma unroll
        for (int ks = 0; ks < 4; ks++) {
            uint32_t a[2][4];
#pragma unroll
            for (int mt = 0; mt < 2; mt++)
                ldsm_x4(a[mt], smb + (uint32_t)(WB[ch & 1] + (m0 + mt * 16) * 72
                                                + ks * 16 + fOff) * 2u);
#pragma unroll
            for (int np = 0; np < 2; np++) {
                uint32_t bb[4];
                ldsm_x4(bb, smb + (uint32_t)(YB[ch & 1] + (n0 + np * 16) * 72
                                             + ks * 16 + fOff) * 2u);
#pragma unroll
                for (int mt = 0; mt < 2; mt++) {
                    mma_f16(acc[mt][2 * np], a[mt], bb[0], bb[2]);
                    mma_f16(acc[mt][2 * np + 1], a[mt], bb[1], bb[3]);
                }
            }
        }
    }

    float sc[2][2], sh[2][2];
#pragma unroll
    for (int mt = 0; mt < 2; mt++)
#pragma unroll
        for (int h = 0; h < 2; h++) {
            int co = cobase + m0 + mt * 16 + g + h * 8;
            float s = bng[co] * rsqrtf(bnv[co] + 1e-5f);
            sc[mt][h] = s;
            sh[mt][h] = bnb[co] - bnm[co] * s + s * wb[co];
        }
#pragma unroll
    for (int mt = 0; mt < 2; mt++) {
#pragma unroll
        for (int j = 0; j < 4; j++) {
            int n = nbase + n0 + j * 8 + 2 * q4;
#pragma unroll
            for (int h = 0; h < 2; h++) {
                int co = cobase + m0 + mt * 16 + g + h * 8;
                size_t base = ((size_t)b * C_ + co) * NQ_ + n;
                float2 xv = *(const float2*)&x[base];
                float2 o;
                o.x = acc[mt][j][2 * h]     * sc[mt][h] + sh[mt][h] + xv.x;
                o.y = acc[mt][j][2 * h + 1] * sc[mt][h] + sh[mt][h] + xv.y;
                *(float2*)&out[base] = o;
            }
        }
    }
}

// ---------------------------------------------------------------------------
extern "C" void kernel_launch(void* const* d_in, const int* in_sizes, int n_in,
                              void* d_out, int out_size) {
    const float* x    = (const float*)d_in[0];
    const float* g_w  = (const float*)d_in[1];
    const float* g_b  = (const float*)d_in[2];
    const float* th_w = (const float*)d_in[3];
    const float* th_b = (const float*)d_in[4];
    const float* ph_w = (const float*)d_in[5];
    const float* ph_b = (const float*)d_in[6];
    const float* w_w  = (const float*)d_in[7];
    const float* w_b  = (const float*)d_in[8];
    const float* bn_g = (const float*)d_in[9];
    const float* bn_b = (const float*)d_in[10];
    const float* bn_m = (const float*)d_in[11];
    const float* bn_v = (const float*)d_in[12];
    float* out = (float*)d_out;

    const int smA = 27648 * 2;   // 55296
    const int smB = 27648 * 2;   // 55296
    const int smC = 35840 * 2;   // 71680
    const int smD = 27648 * 2;   // 55296

    cudaFuncSetAttribute(conv_theta_kernel, cudaFuncAttributeMaxDynamicSharedMemorySize, smA);
    cudaFuncSetAttribute(conv_gphi_kernel,  cudaFuncAttributeMaxDynamicSharedMemorySize, smB);
    cudaFuncSetAttribute(attn_kernel,       cudaFuncAttributeMaxDynamicSharedMemorySize, smC);
    cudaFuncSetAttribute(wconv_kernel,      cudaFuncAttributeMaxDynamicSharedMemorySize, smD);

    prep_kernel<<<dim3(128, 4, 5), 256>>>(x, th_w, g_w, ph_w, w_w);
    conv_theta_kernel<<<dim3(NQ_ / 64, B_), 256, smA>>>(th_b);
    conv_gphi_kernel<<<dim3(128, 2, B_), 256, smB>>>(g_b, ph_b);
    attn_kernel<<<dim3(NQ_ / 128, B_), 256, smC>>>();
    wconv_kernel<<<dim3(NQ_ / 64, 2, B_), 256, smD>>>(x, w_b,
                                                      bn_g, bn_b, bn_m, bn_v, out);
}

// round 14
// speedup vs baseline: 2.0118x; 1.0302x over previous
#include <cuda_runtime.h>
#include <cuda_fp16.h>
#include <math.h>
#include <stdint.h>

#define B_  4
#define C_  256
#define CI_ 128
#define NQ_ 8192
#define NKV_ 2048
#define LOG2E 1.44269504f

// scratch (no cudaMalloc allowed) — all fp16 payloads stored as u16
__device__ unsigned short d_xT  [(size_t)B_ * NQ_ * C_];   // (b, n, c)
__device__ unsigned short twr   [CI_ * C_];
__device__ unsigned short gwr   [CI_ * C_];
__device__ unsigned short pwr   [CI_ * C_];
__device__ unsigned short wwr   [C_ * CI_];
__device__ unsigned short d_theta[(size_t)B_ * NQ_ * CI_]; // (b, n, ci) pre-scaled by log2e
__device__ unsigned short d_key  [(size_t)B_ * NKV_ * CI_];// (b, m, ci)
__device__ unsigned short d_valT [(size_t)B_ * CI_ * NKV_];// (b, ci, m)
__device__ unsigned short d_yy   [(size_t)B_ * NQ_ * CI_]; // (b, n, ci)

__device__ __forceinline__ uint32_t f2h2(float lo, float hi) {
    uint32_t r;
    asm("cvt.rn.f16x2.f32 %0, %1, %2;" : "=r"(r) : "f"(hi), "f"(lo));
    return r;
}

__device__ __forceinline__ void mma_f16(float* c, const uint32_t* a,
                                        uint32_t b0, uint32_t b1) {
    asm volatile(
        "mma.sync.aligned.m16n8k16.row.col.f32.f16.f16.f32 "
        "{%0,%1,%2,%3}, {%4,%5,%6,%7}, {%8,%9}, {%0,%1,%2,%3};"
        : "+f"(c[0]), "+f"(c[1]), "+f"(c[2]), "+f"(c[3])
        : "r"(a[0]), "r"(a[1]), "r"(a[2]), "r"(a[3]), "r"(b0), "r"(b1));
}

__device__ __forceinline__ void ldsm_x4(uint32_t* r, uint32_t a) {
    asm volatile("ldmatrix.sync.aligned.m8n8.x4.shared.b16 {%0,%1,%2,%3}, [%4];"
                 : "=r"(r[0]), "=r"(r[1]), "=r"(r[2]), "=r"(r[3]) : "r"(a));
}

__device__ __forceinline__ void cpa(uint32_t dst, const void* src) {
    asm volatile("cp.async.cg.shared.global [%0], [%1], 16;" :: "r"(dst), "l"(src));
}
#define CP_COMMIT() asm volatile("cp.async.commit_group;")
#define CP_WAIT0()  asm volatile("cp.async.wait_group 0;")

// fragment base offsets (in halves): row = lane&15, k-half = lane>>4
#define FRAG_OFF(stride) ((lane & 15) * (stride) + (lane >> 4) * 8)

// ---------------------------------------------------------------------------
// Prep: z<4 -> transpose+round x slice to fp16; z==4 -> round weights.
// ---------------------------------------------------------------------------
__global__ void __launch_bounds__(256) prep_kernel(
        const float* __restrict__ x,
        const float* __restrict__ tw, const float* __restrict__ gw,
        const float* __restrict__ pw, const float* __restrict__ ww) {
    if (blockIdx.z == 4) {
        int bid = blockIdx.y * 128 + blockIdx.x;
        if (bid >= 16) return;
        int i = (bid * 256 + threadIdx.x) * 8;
        float4 v0, v1;
        uint2 o;
        v0 = *(const float4*)&tw[i]; v1 = *(const float4*)&tw[i + 4];
        o.x = f2h2(v0.x, v0.y); o.y = f2h2(v0.z, v0.w);
        *(uint2*)&twr[i] = o;
        o.x = f2h2(v1.x, v1.y); o.y = f2h2(v1.z, v1.w);
        *(uint2*)&twr[i + 4] = o;
        v0 = *(const float4*)&gw[i]; v1 = *(const float4*)&gw[i + 4];
        o.x = f2h2(v0.x, v0.y); o.y = f2h2(v0.z, v0.w);
        *(uint2*)&gwr[i] = o;
        o.x = f2h2(v1.x, v1.y); o.y = f2h2(v1.z, v1.w);
        *(uint2*)&gwr[i + 4] = o;
        v0 = *(const float4*)&pw[i]; v1 = *(const float4*)&pw[i + 4];
        o.x = f2h2(v0.x, v0.y); o.y = f2h2(v0.z, v0.w);
        *(uint2*)&pwr[i] = o;
        o.x = f2h2(v1.x, v1.y); o.y = f2h2(v1.z, v1.w);
        *(uint2*)&pwr[i + 4] = o;
        v0 = *(const float4*)&ww[i]; v1 = *(const float4*)&ww[i + 4];
        o.x = f2h2(v0.x, v0.y); o.y = f2h2(v0.z, v0.w);
        *(uint2*)&wwr[i] = o;
        o.x = f2h2(v1.x, v1.y); o.y = f2h2(v1.z, v1.w);
        *(uint2*)&wwr[i + 4] = o;
        return;
    }
    __shared__ float Ts[64 * 65];
    const int b = blockIdx.z, cb = blockIdx.y * 64, nb = blockIdx.x * 64;
    const int tid = threadIdx.x;
#pragma unroll
    for (int u = 0; u < 4; u++) {
        int idx = u * 256 + tid;
        int cc = idx >> 4, j4 = idx & 15;
        float4 v = *(const float4*)&x[((size_t)b * C_ + cb + cc) * NQ_ + nb + j4 * 4];
        Ts[(j4 * 4 + 0) * 65 + cc] = v.x;
        Ts[(j4 * 4 + 1) * 65 + cc] = v.y;
        Ts[(j4 * 4 + 2) * 65 + cc] = v.z;
        Ts[(j4 * 4 + 3) * 65 + cc] = v.w;
    }
    __syncthreads();
#pragma unroll
    for (int u = 0; u < 4; u++) {
        int idx = u * 256 + tid;
        int nn = idx >> 4, c4 = idx & 15;
        uint2 o;
        o.x = f2h2(Ts[nn * 65 + c4 * 4], Ts[nn * 65 + c4 * 4 + 1]);
        o.y = f2h2(Ts[nn * 65 + c4 * 4 + 2], Ts[nn * 65 + c4 * 4 + 3]);
        *(uint2*)&d_xT[((size_t)b * NQ_ + nb + nn) * C_ + cb + c4 * 4] = o;
    }
}

// ---------------------------------------------------------------------------
// Kernel A: theta conv fp16 (epilogue scaled by LOG2E). Same as R13.
// ---------------------------------------------------------------------------
__global__ void __launch_bounds__(256, 2) conv_theta_kernel(const float* __restrict__ tb) {
    extern __shared__ unsigned short smh[];
    const int b = blockIdx.y;
    const int nbase = blockIdx.x * 64;
    const int tid = threadIdx.x;
    const int warp = tid >> 5, lane = tid & 31;
    const int g = lane >> 2, q4 = lane & 3;
    const int m0 = (warp >> 2) * 32;
    const int n0 = (warp & 3) * 32;
    const uint32_t smb = (uint32_t)__cvta_generic_to_shared(smh);
    const uint32_t XB[2] = {0u, 4608u}, WB[2] = {9216u, 18432u};
    const int fOff = FRAG_OFF(72);

    float acc[2][4][4];
#pragma unroll
    for (int i = 0; i < 2; i++)
#pragma unroll
        for (int j = 0; j < 4; j++)
#pragma unroll
            for (int k = 0; k < 4; k++) acc[i][j][k] = 0.f;

    const unsigned short* xb = d_xT + ((size_t)b * NQ_ + nbase) * C_;

#pragma unroll
    for (int u = 0; u < 2; u++) {
        int idx = u * 256 + tid;
        int r = idx >> 3, c8 = idx & 7;
        cpa(smb + (XB[0] + r * 72 + c8 * 8) * 2u, xb + (size_t)r * C_ + c8 * 8);
    }
#pragma unroll
    for (int u = 0; u < 4; u++) {
        int idx = u * 256 + tid;
        int r = idx >> 3, c8 = idx & 7;
        cpa(smb + (WB[0] + r * 72 + c8 * 8) * 2u, &twr[r * C_ + c8 * 8]);
    }
    CP_COMMIT();

    for (int ch = 0; ch < 4; ch++) {
        CP_WAIT0();
        __syncthreads();
        if (ch < 3) {
            int c0 = (ch + 1) * 64, buf = (ch + 1) & 1;
#pragma unroll
            for (int u = 0; u < 2; u++) {
                int idx = u * 256 + tid;
                int r = idx >> 3, c8 = idx & 7;
                cpa(smb + (XB[buf] + r * 72 + c8 * 8) * 2u, xb + (size_t)r * C_ + c0 + c8 * 8);
            }
#pragma unroll
            for (int u = 0; u < 4; u++) {
                int idx = u * 256 + tid;
                int r = idx >> 3, c8 = idx & 7;
                cpa(smb + (WB[buf] + r * 72 + c8 * 8) * 2u, &twr[r * C_ + c0 + c8 * 8]);
            }
            CP_COMMIT();
        }
#pragma unroll
        for (int ks = 0; ks < 4; ks++) {
            uint32_t a[2][4];
#pragma unroll
            for (int mt = 0; mt < 2; mt++)
                ldsm_x4(a[mt], smb + (uint32_t)(XB[ch & 1] + (m0 + mt * 16) * 72
                                                + ks * 16 + fOff) * 2u);
#pragma unroll
            for (int np = 0; np < 2; np++) {
                uint32_t bb[4];
                ldsm_x4(bb, smb + (uint32_t)(WB[ch & 1] + (n0 + np * 16) * 72
                                             + ks * 16 + fOff) * 2u);
#pragma unroll
                for (int mt = 0; mt < 2; mt++) {
                    mma_f16(acc[mt][2 * np], a[mt], bb[0], bb[2]);
                    mma_f16(acc[mt][2 * np + 1], a[mt], bb[1], bb[3]);
                }
            }
        }
    }
#pragma unroll
    for (int j = 0; j < 4; j++) {
        int o = n0 + j * 8 + 2 * q4;
        float b0 = tb[o], b1 = tb[o + 1];
#pragma unroll
        for (int mt = 0; mt < 2; mt++) {
            size_t r = (size_t)b * NQ_ + nbase + m0 + mt * 16 + g;
            *(uint32_t*)&d_theta[r * CI_ + o] =
                f2h2((acc[mt][j][0] + b0) * LOG2E, (acc[mt][j][1] + b1) * LOG2E);
            *(uint32_t*)&d_theta[(r + 8) * CI_ + o] =
                f2h2((acc[mt][j][2] + b0) * LOG2E, (acc[mt][j][3] + b1) * LOG2E);
        }
    }
}

// ---------------------------------------------------------------------------
// Kernel B: g/phi conv + maxpool fp16. Same as R13.
// ---------------------------------------------------------------------------
__global__ void __launch_bounds__(256, 2) conv_gphi_kernel(
        const float* __restrict__ gb, const float* __restrict__ pb) {
    extern __shared__ unsigned short smh[];
    const int b = blockIdx.z;
    const int ob = blockIdx.y;
    const int t = blockIdx.x >> 4, hp = blockIdx.x & 15;
    const int nbase = t * 1024 + hp * 64;
    const int tid = threadIdx.x;
    const int warp = tid >> 5, lane = tid & 31;
    const int g = lane >> 2, q4 = lane & 3;
    const int m0 = (warp >> 2) * 32;
    const int n0 = (warp & 3) * 16;
    const uint32_t smb = (uint32_t)__cvta_generic_to_shared(smh);
    const uint32_t XB[2] = {0u, 4608u}, GB[2] = {9216u, 13824u}, PB[2] = {18432u, 23040u};
    const int fOff = FRAG_OFF(72);

    float ag[2][2][4], ap[2][2][4];
#pragma unroll
    for (int i = 0; i < 2; i++)
#pragma unroll
        for (int j = 0; j < 2; j++)
#pragma unroll
            for (int k = 0; k < 4; k++) { ag[i][j][k] = 0.f; ap[i][j][k] = 0.f; }

    const unsigned short* xb = d_xT + ((size_t)b * NQ_ + nbase) * C_;
    const unsigned short* gwb = gwr + (ob * 64) * C_;
    const unsigned short* pwb = pwr + (ob * 64) * C_;

#pragma unroll
    for (int u = 0; u < 2; u++) {
        int idx = u * 256 + tid;
        int r = idx >> 3, c8 = idx & 7;
        cpa(smb + (XB[0] + r * 72 + c8 * 8) * 2u, xb + (size_t)r * C_ + c8 * 8);
        cpa(smb + (GB[0] + r * 72 + c8 * 8) * 2u, gwb + r * C_ + c8 * 8);
        cpa(smb + (PB[0] + r * 72 + c8 * 8) * 2u, pwb + r * C_ + c8 * 8);
    }
    CP_COMMIT();

    for (int ch = 0; ch < 4; ch++) {
        CP_WAIT0();
        __syncthreads();
        if (ch < 3) {
            int c0 = (ch + 1) * 64, buf = (ch + 1) & 1;
#pragma unroll
            for (int u = 0; u < 2; u++) {
                int idx = u * 256 + tid;
                int r = idx >> 3, c8 = idx & 7;
                cpa(smb + (XB[buf] + r * 72 + c8 * 8) * 2u, xb + (size_t)r * C_ + c0 + c8 * 8);
                cpa(smb + (GB[buf] + r * 72 + c8 * 8) * 2u, gwb + r * C_ + c0 + c8 * 8);
                cpa(smb + (PB[buf] + r * 72 + c8 * 8) * 2u, pwb + r * C_ + c0 + c8 * 8);
            }
            CP_COMMIT();
        }
#pragma unroll
        for (int ks = 0; ks < 4; ks++) {
            uint32_t a[2][4];
#pragma unroll
            for (int mt = 0; mt < 2; mt++)
                ldsm_x4(a[mt], smb + (uint32_t)(XB[ch & 1] + (m0 + mt * 16) * 72
                                                + ks * 16 + fOff) * 2u);
            uint32_t bg_[4], bp_[4];
            ldsm_x4(bg_, smb + (uint32_t)(GB[ch & 1] + n0 * 72 + ks * 16 + fOff) * 2u);
            ldsm_x4(bp_, smb + (uint32_t)(PB[ch & 1] + n0 * 72 + ks * 16 + fOff) * 2u);
#pragma unroll
            for (int mt = 0; mt < 2; mt++) {
                mma_f16(ag[mt][0], a[mt], bg_[0], bg_[2]);
                mma_f16(ag[mt][1], a[mt], bg_[1], bg_[3]);
                mma_f16(ap[mt][0], a[mt], bp_[0], bp_[2]);
                mma_f16(ap[mt][1], a[mt], bp_[1], bp_[3]);
            }
        }
    }
    __syncthreads();
    float* Sg = (float*)smh;            // [64][68]
    float* Sp = (float*)smh + 4352;     // [64][68]
    float* Pv = (float*)smh + 8704;     // [64][20]
#pragma unroll
    for (int mt = 0; mt < 2; mt++) {
#pragma unroll
        for (int j = 0; j < 2; j++) {
            int r = m0 + mt * 16 + g;
            int o = n0 + j * 8 + 2 * q4;
            *(float2*)&Sg[r * 68 + o] = *(float2*)&ag[mt][j][0];
            *(float2*)&Sg[(r + 8) * 68 + o] = *(float2*)&ag[mt][j][2];
            *(float2*)&Sp[r * 68 + o] = *(float2*)&ap[mt][j][0];
            *(float2*)&Sp[(r + 8) * 68 + o] = *(float2*)&ap[mt][j][2];
        }
    }
    __syncthreads();
    const int mb = t * 256 + hp * 16;
    {
        int p = tid >> 4, o4 = (tid & 15) * 4;
        float4 bgv = *(const float4*)&gb[ob * 64 + o4];
        float4 bpv = *(const float4*)&pb[ob * 64 + o4];
        float4 r0, r1, r2, r3;
        r0 = *(float4*)&Sp[(2 * p) * 68 + o4];
        r1 = *(float4*)&Sp[(2 * p + 1) * 68 + o4];
        r2 = *(float4*)&Sp[(32 + 2 * p) * 68 + o4];
        r3 = *(float4*)&Sp[(33 + 2 * p) * 68 + o4];
        uint2 ko;
        ko.x = f2h2(fmaxf(fmaxf(r0.x, r1.x), fmaxf(r2.x, r3.x)) + bpv.x,
                    fmaxf(fmaxf(r0.y, r1.y), fmaxf(r2.y, r3.y)) + bpv.y);
        ko.y = f2h2(fmaxf(fmaxf(r0.z, r1.z), fmaxf(r2.z, r3.z)) + bpv.z,
                    fmaxf(fmaxf(r0.w, r1.w), fmaxf(r2.w, r3.w)) + bpv.w);
        *(uint2*)&d_key[((size_t)b * NKV_ + mb + p) * CI_ + ob * 64 + o4] = ko;
        r0 = *(float4*)&Sg[(2 * p) * 68 + o4];
        r1 = *(float4*)&Sg[(2 * p + 1) * 68 + o4];
        r2 = *(float4*)&Sg[(32 + 2 * p) * 68 + o4];
        r3 = *(float4*)&Sg[(33 + 2 * p) * 68 + o4];
        Pv[(o4 + 0) * 20 + p] = fmaxf(fmaxf(r0.x, r1.x), fmaxf(r2.x, r3.x)) + bgv.x;
        Pv[(o4 + 1) * 20 + p] = fmaxf(fmaxf(r0.y, r1.y), fmaxf(r2.y, r3.y)) + bgv.y;
        Pv[(o4 + 2) * 20 + p] = fmaxf(fmaxf(r0.z, r1.z), fmaxf(r2.z, r3.z)) + bgv.z;
        Pv[(o4 + 3) * 20 + p] = fmaxf(fmaxf(r0.w, r1.w), fmaxf(r2.w, r3.w)) + bgv.w;
    }
    __syncthreads();
    {
        int ci = tid >> 2, j = (tid & 3) * 4;
        uint2 v;
        v.x = f2h2(Pv[ci * 20 + j], Pv[ci * 20 + j + 1]);
        v.y = f2h2(Pv[ci * 20 + j + 2], Pv[ci * 20 + j + 3]);
        *(uint2*)&d_valT[((size_t)b * CI_ + ob * 64 + ci) * NKV_ + mb + j] = v;
    }
}

// ---------------------------------------------------------------------------
// Kernel C: fp16 flash attention, R13 numerics + compile-time double-buffer
// (unroll-2) + hoisted per-thread cp.async/LDSM offsets.
// smem halves: K0@0 K1@8704 ([64][136]); V0@17408 V1@26624 ([128][72]).
// ---------------------------------------------------------------------------
__global__ void __launch_bounds__(256, 1) attn_kernel() {
    extern __shared__ unsigned short smh[];
    const int b = blockIdx.y;
    const int qbase = blockIdx.x * 128;
    const int tid = threadIdx.x;
    const int warp = tid >> 5, lane = tid & 31;
    const int g = lane >> 2, q4 = lane & 3;
    const int r0 = warp * 16 + g;
    const uint32_t smb = (uint32_t)__cvta_generic_to_shared(smh);
    const uint32_t KB0 = 0u, KB1 = 8704u, VB0 = 17408u, VB1 = 26624u;

    const unsigned short* qb = d_theta + ((size_t)b * NQ_ + qbase) * CI_;
    const unsigned short* keyb = d_key + (size_t)b * NKV_ * CI_;
    const unsigned short* valb = d_valT + (size_t)b * CI_ * NKV_;

    // hoisted per-thread copy offsets (loop-invariant)
    int kgo[4], kso[4], vgo[4], vso[4];
#pragma unroll
    for (int u = 0; u < 4; u++) {
        int idx = u * 256 + tid;
        int rk = idx >> 4, ck = idx & 15;
        kgo[u] = rk * CI_ + ck * 8;
        kso[u] = (rk * 136 + ck * 8) * 2;
        int rv = idx >> 3, cv = idx & 7;
        vgo[u] = rv * NKV_ + cv * 8;
        vso[u] = (rv * 72 + cv * 8) * 2;
    }

    // stage Q (over K region) + V0
#pragma unroll
    for (int u = 0; u < 8; u++) {
        int idx = u * 256 + tid;
        int r = idx >> 4, c8 = idx & 15;
        cpa(smb + (uint32_t)(r * 136 + c8 * 8) * 2u, qb + (size_t)r * CI_ + c8 * 8);
    }
#pragma unroll
    for (int u = 0; u < 4; u++)
        cpa(smb + VB0 * 2u + vso[u], valb + vgo[u]);
    CP_COMMIT();
    CP_WAIT0();
    __syncthreads();

    uint32_t qfrag[8][4];
    {
        const uint32_t aQ = (uint32_t)((lane & 15) * 136 + (lane >> 4) * 8);
#pragma unroll
        for (int ks = 0; ks < 8; ks++)
            ldsm_x4(qfrag[ks], smb + (uint32_t)(warp * 16 * 136 + ks * 16 + aQ) * 2u);
    }
    __syncthreads();
#pragma unroll
    for (int u = 0; u < 4; u++)
        cpa(smb + KB0 * 2u + kso[u], keyb + kgo[u]);
    CP_COMMIT();

    // hoisted LDSM lane bases (byte addresses) per buffer
    const uint32_t kA[2] = {smb + KB0 * 2u + (uint32_t)FRAG_OFF(136) * 2u,
                            smb + KB1 * 2u + (uint32_t)FRAG_OFF(136) * 2u};
    const uint32_t vA[2] = {smb + VB0 * 2u + (uint32_t)FRAG_OFF(72) * 2u,
                            smb + VB1 * 2u + (uint32_t)FRAG_OFF(72) * 2u};
    const uint32_t kS[2] = {smb + KB0 * 2u, smb + KB1 * 2u};
    const uint32_t vS[2] = {smb + VB0 * 2u, smb + VB1 * 2u};

    float m[2] = {-3.0e38f, -3.0e38f}, l[2] = {0.f, 0.f};
    float oacc[16][4];
#pragma unroll
    for (int i = 0; i < 16; i++)
#pragma unroll
        for (int j = 0; j < 4; j++) oacc[i][j] = 0.f;

    for (int it = 0; it < 16; it++) {
#pragma unroll
        for (int hb = 0; hb < 2; hb++) {
            const int mt = it * 2 + hb;
            CP_WAIT0();
            __syncthreads();
            if (mt + 1 < 32) {
                const int nb = (mt + 1) * 64;
                const unsigned short* ksrc = keyb + (size_t)nb * CI_;
                const unsigned short* vsrc = valb + nb;
#pragma unroll
                for (int u = 0; u < 4; u++)
                    cpa(kS[hb ^ 1] + kso[u], ksrc + kgo[u]);
#pragma unroll
                for (int u = 0; u < 4; u++)
                    cpa(vS[hb ^ 1] + vso[u], vsrc + vgo[u]);
                CP_COMMIT();
            }

            // S = Q K^T (log2 units): 8 ks(k16) x 4 n16-groups, const offsets
            float sacc[8][4];
#pragma unroll
            for (int i = 0; i < 8; i++)
#pragma unroll
                for (int j = 0; j < 4; j++) sacc[i][j] = 0.f;
#pragma unroll
            for (int ks = 0; ks < 8; ks++) {
#pragma unroll
                for (int np = 0; np < 4; np++) {
                    uint32_t bb[4];
                    ldsm_x4(bb, kA[hb] + (uint32_t)(np * 16 * 136 + ks * 16) * 2u);
                    mma_f16(sacc[2 * np], qfrag[ks], bb[0], bb[2]);
                    mma_f16(sacc[2 * np + 1], qfrag[ks], bb[1], bb[3]);
                }
            }

            // online softmax; rescale only when row max rises
#pragma unroll
            for (int h = 0; h < 2; h++) {
                float tmax = -3.0e38f;
#pragma unroll
                for (int nt = 0; nt < 8; nt++)
                    tmax = fmaxf(tmax, fmaxf(sacc[nt][2 * h], sacc[nt][2 * h + 1]));
                tmax = fmaxf(tmax, __shfl_xor_sync(0xffffffffu, tmax, 1));
                tmax = fmaxf(tmax, __shfl_xor_sync(0xffffffffu, tmax, 2));
                if (tmax > m[h]) {
                    float fac = exp2f(m[h] - tmax);
                    m[h] = tmax;
                    l[h] *= fac;
#pragma unroll
                    for (int ot = 0; ot < 16; ot++) {
                        oacc[ot][2 * h]     *= fac;
                        oacc[ot][2 * h + 1] *= fac;
                    }
                }
            }

#pragma unroll
            for (int nt = 0; nt < 8; nt++) {
                float e0 = exp2f(sacc[nt][0] - m[0]);
                float e1 = exp2f(sacc[nt][1] - m[0]);
                float e2 = exp2f(sacc[nt][2] - m[1]);
                float e3 = exp2f(sacc[nt][3] - m[1]);
                l[0] += e0 + e1;
                l[1] += e2 + e3;
                sacc[nt][0] = e0; sacc[nt][1] = e1;
                sacc[nt][2] = e2; sacc[nt][3] = e3;
            }

            // O += P V : P fragments straight from registers, const offsets
#pragma unroll
            for (int ks = 0; ks < 4; ks++) {
                uint32_t a[4];
                a[0] = f2h2(sacc[2 * ks][0], sacc[2 * ks][1]);
                a[1] = f2h2(sacc[2 * ks][2], sacc[2 * ks][3]);
                a[2] = f2h2(sacc[2 * ks + 1][0], sacc[2 * ks + 1][1]);
                a[3] = f2h2(sacc[2 * ks + 1][2], sacc[2 * ks + 1][3]);
#pragma unroll
                for (int np = 0; np < 8; np++) {
                    uint32_t bb[4];
                    ldsm_x4(bb, vA[hb] + (uint32_t)(np * 16 * 72 + ks * 16) * 2u);
                    mma_f16(oacc[2 * np], a, bb[0], bb[2]);
                    mma_f16(oacc[2 * np + 1], a, bb[1], bb[3]);
                }
            }
        }
    }

    // deferred l lane-reduction, normalize, write
#pragma unroll
    for (int h = 0; h < 2; h++) {
        l[h] += __shfl_xor_sync(0xffffffffu, l[h], 1);
        l[h] += __shfl_xor_sync(0xffffffffu, l[h], 2);
    }
    float inv0 = 1.f / l[0], inv1 = 1.f / l[1];
    size_t row0 = (size_t)b * NQ_ + qbase + r0;
#pragma unroll
    for (int nt = 0; nt < 16; nt++) {
        int ci = nt * 8 + 2 * q4;
        *(uint32_t*)&d_yy[row0 * CI_ + ci] = f2h2(oacc[nt][0] * inv0, oacc[nt][1] * inv0);
        *(uint32_t*)&d_yy[(row0 + 8) * CI_ + ci] = f2h2(oacc[nt][2] * inv1, oacc[nt][3] * inv1);
    }
}

// ---------------------------------------------------------------------------
// Kernel D: wconv + BN + residual fp16. Same as R13.
// ---------------------------------------------------------------------------
__global__ void __launch_bounds__(256, 2) wconv_kernel(
        const float* __restrict__ x,
        const float* __restrict__ wb,
        const float* __restrict__ bng, const float* __restrict__ bnb,
        const float* __restrict__ bnm, const float* __restrict__ bnv,
        float* __restrict__ out) {
    extern __shared__ unsigned short smh[];
    const int b = blockIdx.z;
    const int cobase = blockIdx.y * 128;
    const int nbase = blockIdx.x * 64;
    const int tid = threadIdx.x;
    const int warp = tid >> 5, lane = tid & 31;
    const int g = lane >> 2, q4 = lane & 3;
    const int m0 = (warp >> 1) * 32;
    const int n0 = (warp & 1) * 32;
    const uint32_t smb = (uint32_t)__cvta_generic_to_shared(smh);
    const uint32_t WB[2] = {0u, 9216u}, YB[2] = {18432u, 23040u};
    const int fOff = FRAG_OFF(72);

    float acc[2][4][4];
#pragma unroll
    for (int i = 0; i < 2; i++)
#pragma unroll
        for (int j = 0; j < 4; j++)
#pragma unroll
            for (int k = 0; k < 4; k++) acc[i][j][k] = 0.f;

    const unsigned short* yb = d_yy + ((size_t)b * NQ_ + nbase) * CI_;

#pragma unroll
    for (int u = 0; u < 4; u++) {
        int idx = u * 256 + tid;
        int r = idx >> 3, c8 = idx & 7;
        cpa(smb + (WB[0] + r * 72 + c8 * 8) * 2u, &wwr[(cobase + r) * CI_ + c8 * 8]);
    }
#pragma unroll
    for (int u = 0; u < 2; u++) {
        int idx = u * 256 + tid;
        int r = idx >> 3, c8 = idx & 7;
        cpa(smb + (YB[0] + r * 72 + c8 * 8) * 2u, yb + (size_t)r * CI_ + c8 * 8);
    }
    CP_COMMIT();

    for (int ch = 0; ch < 2; ch++) {
        CP_WAIT0();
        __syncthreads();
        if (ch < 1) {
#pragma unroll
            for (int u = 0; u < 4; u++) {
                int idx = u * 256 + tid;
                int r = idx >> 3, c8 = idx & 7;
                cpa(smb + (WB[1] + r * 72 + c8 * 8) * 2u,
                    &wwr[(cobase + r) * CI_ + 64 + c8 * 8]);
            }
#pragma unroll
            for (int u = 0; u < 2; u++) {
                int idx = u * 256 + tid;
                int r = idx >> 3, c8 = idx & 7;
                cpa(smb + (YB[1] + r * 72 + c8 * 8) * 2u,
                    yb + (size_t)r * CI_ + 64 + c8 * 8);
            }
            CP_COMMIT();
        }
#pragma unroll
        for (int ks = 0; ks < 4; ks++) {
            uint32_t a[2][4];
#pragma unroll
            for (int mt = 0; mt < 2; mt++)
                ldsm_x4(a[mt], smb + (uint32_t)(WB[ch & 1] + (m0 + mt * 16) * 72
                                                + ks * 16 + fOff) * 2u);
#pragma unroll
            for (int np = 0; np < 2; np++) {
                uint32_t bb[4];
                ldsm_x4(bb, smb + (uint32_t)(YB[ch & 1] + (n0 + np * 16) * 72
                                             + ks * 16 + fOff) * 2u);
#pragma unroll
                for (int mt = 0; mt < 2; mt++) {
                    mma_f16(acc[mt][2 * np], a[mt], bb[0], bb[2]);
                    mma_f16(acc[mt][2 * np + 1], a[mt], bb[1], bb[3]);
                }
            }
        }
    }

    float sc[2][2], sh[2][2];
#pragma unroll
    for (int mt = 0; mt < 2; mt++)
#pragma unroll
        for (int h = 0; h < 2; h++) {
            int co = cobase + m0 + mt * 16 + g + h * 8;
            float s = bng[co] * rsqrtf(bnv[co] + 1e-5f);
            sc[mt][h] = s;
            sh[mt][h] = bnb[co] - bnm[co] * s + s * wb[co];
        }
#pragma unroll
    for (int mt = 0; mt < 2; mt++) {
#pragma unroll
        for (int j = 0; j < 4; j++) {
            int n = nbase + n0 + j * 8 + 2 * q4;
#pragma unroll
            for (int h = 0; h < 2; h++) {
                int co = cobase + m0 + mt * 16 + g + h * 8;
                size_t base = ((size_t)b * C_ + co) * NQ_ + n;
                float2 xv = *(const float2*)&x[base];
                float2 o;
                o.x = acc[mt][j][2 * h]     * sc[mt][h] + sh[mt][h] + xv.x;
                o.y = acc[mt][j][2 * h + 1] * sc[mt][h] + sh[mt][h] + xv.y;
                *(float2*)&out[base] = o;
            }
        }
    }
}

// ---------------------------------------------------------------------------
extern "C" void kernel_launch(void* const* d_in, const int* in_sizes, int n_in,
                              void* d_out, int out_size) {
    const float* x    = (const float*)d_in[0];
    const float* g_w  = (const float*)d_in[1];
    const float* g_b  = (const float*)d_in[2];
    const float* th_w = (const float*)d_in[3];
    const float* th_b = (const float*)d_in[4];
    const float* ph_w = (const float*)d_in[5];
    const float* ph_b = (const float*)d_in[6];
    const float* w_w  = (const float*)d_in[7];
    const float* w_b  = (const float*)d_in[8];
    const float* bn_g = (const float*)d_in[9];
    const float* bn_b = (const float*)d_in[10];
    const float* bn_m = (const float*)d_in[11];
    const float* bn_v = (const float*)d_in[12];
    float* out = (float*)d_out;

    const int smA = 27648 * 2;   // 55296
    const int smB = 27648 * 2;   // 55296
    const int smC = 35840 * 2;   // 71680
    const int smD = 27648 * 2;   // 55296

    cudaFuncSetAttribute(conv_theta_kernel, cudaFuncAttributeMaxDynamicSharedMemorySize, smA);
    cudaFuncSetAttribute(conv_gphi_kernel,  cudaFuncAttributeMaxDynamicSharedMemorySize, smB);
    cudaFuncSetAttribute(attn_kernel,       cudaFuncAttributeMaxDynamicSharedMemorySize, smC);
    cudaFuncSetAttribute(wconv_kernel,      cudaFuncAttributeMaxDynamicSharedMemorySize, smD);

    prep_kernel<<<dim3(128, 4, 5), 256>>>(x, th_w, g_w, ph_w, w_w);
    conv_theta_kernel<<<dim3(NQ_ / 64, B_), 256, smA>>>(th_b);
    conv_gphi_kernel<<<dim3(128, 2, B_), 256, smB>>>(g_b, ph_b);
    attn_kernel<<<dim3(NQ_ / 128, B_), 256, smC>>>();
    wconv_kernel<<<dim3(NQ_ / 64, 2, B_), 256, smD>>>(x, w_b,
                                                      bn_g, bn_b, bn_m, bn_v, out);
}

// round 16
// speedup vs baseline: 2.1063x; 1.0470x over previous
#include <cuda_runtime.h>
#include <cuda_fp16.h>
#include <math.h>
#include <stdint.h>

#define B_  4
#define C_  256
#define CI_ 128
#define NQ_ 8192
#define NKV_ 2048
#define LOG2E 1.44269504f

// scratch (no cudaMalloc allowed) — all fp16 payloads stored as u16
__device__ unsigned short d_xT  [(size_t)B_ * NQ_ * C_];   // (b, n, c)
__device__ unsigned short twr   [CI_ * C_];
__device__ unsigned short gwr   [CI_ * C_];
__device__ unsigned short pwr   [CI_ * C_];
__device__ unsigned short wwr   [C_ * CI_];
__device__ unsigned short d_theta[(size_t)B_ * NQ_ * CI_]; // (b, n, ci) pre-scaled by log2e
__device__ unsigned short d_key  [(size_t)B_ * NKV_ * CI_];// (b, m, ci)
__device__ unsigned short d_valT [(size_t)B_ * CI_ * NKV_];// (b, ci, m)
__device__ unsigned short d_yy   [(size_t)B_ * NQ_ * CI_]; // (b, n, ci)

__device__ __forceinline__ uint32_t f2h2(float lo, float hi) {
    uint32_t r;
    asm("cvt.rn.f16x2.f32 %0, %1, %2;" : "=r"(r) : "f"(hi), "f"(lo));
    return r;
}

__device__ __forceinline__ void mma_f16(float* c, const uint32_t* a,
                                        uint32_t b0, uint32_t b1) {
    asm volatile(
        "mma.sync.aligned.m16n8k16.row.col.f32.f16.f16.f32 "
        "{%0,%1,%2,%3}, {%4,%5,%6,%7}, {%8,%9}, {%0,%1,%2,%3};"
        : "+f"(c[0]), "+f"(c[1]), "+f"(c[2]), "+f"(c[3])
        : "r"(a[0]), "r"(a[1]), "r"(a[2]), "r"(a[3]), "r"(b0), "r"(b1));
}

__device__ __forceinline__ void ldsm_x4(uint32_t* r, uint32_t a) {
    asm volatile("ldmatrix.sync.aligned.m8n8.x4.shared.b16 {%0,%1,%2,%3}, [%4];"
                 : "=r"(r[0]), "=r"(r[1]), "=r"(r[2]), "=r"(r[3]) : "r"(a));
}

__device__ __forceinline__ void cpa(uint32_t dst, const void* src) {
    asm volatile("cp.async.cg.shared.global [%0], [%1], 16;" :: "r"(dst), "l"(src));
}
#define CP_COMMIT() asm volatile("cp.async.commit_group;")
#define CP_WAIT0()  asm volatile("cp.async.wait_group 0;")

// fragment base offsets (in halves): row = lane&15, k-half = lane>>4
#define FRAG_OFF(stride) ((lane & 15) * (stride) + (lane >> 4) * 8)

// ---------------------------------------------------------------------------
// Prep: z<4 -> transpose+round x slice to fp16; z==4 -> round weights.
// ---------------------------------------------------------------------------
__global__ void __launch_bounds__(256) prep_kernel(
        const float* __restrict__ x,
        const float* __restrict__ tw, const float* __restrict__ gw,
        const float* __restrict__ pw, const float* __restrict__ ww) {
    if (blockIdx.z == 4) {
        int bid = blockIdx.y * 128 + blockIdx.x;
        if (bid >= 16) return;
        int i = (bid * 256 + threadIdx.x) * 8;
        float4 v0, v1;
        uint2 o;
        v0 = *(const float4*)&tw[i]; v1 = *(const float4*)&tw[i + 4];
        o.x = f2h2(v0.x, v0.y); o.y = f2h2(v0.z, v0.w);
        *(uint2*)&twr[i] = o;
        o.x = f2h2(v1.x, v1.y); o.y = f2h2(v1.z, v1.w);
        *(uint2*)&twr[i + 4] = o;
        v0 = *(const float4*)&gw[i]; v1 = *(const float4*)&gw[i + 4];
        o.x = f2h2(v0.x, v0.y); o.y = f2h2(v0.z, v0.w);
        *(uint2*)&gwr[i] = o;
        o.x = f2h2(v1.x, v1.y); o.y = f2h2(v1.z, v1.w);
        *(uint2*)&gwr[i + 4] = o;
        v0 = *(const float4*)&pw[i]; v1 = *(const float4*)&pw[i + 4];
        o.x = f2h2(v0.x, v0.y); o.y = f2h2(v0.z, v0.w);
        *(uint2*)&pwr[i] = o;
        o.x = f2h2(v1.x, v1.y); o.y = f2h2(v1.z, v1.w);
        *(uint2*)&pwr[i + 4] = o;
        v0 = *(const float4*)&ww[i]; v1 = *(const float4*)&ww[i + 4];
        o.x = f2h2(v0.x, v0.y); o.y = f2h2(v0.z, v0.w);
        *(uint2*)&wwr[i] = o;
        o.x = f2h2(v1.x, v1.y); o.y = f2h2(v1.z, v1.w);
        *(uint2*)&wwr[i + 4] = o;
        return;
    }
    __shared__ float Ts[64 * 65];
    const int b = blockIdx.z, cb = blockIdx.y * 64, nb = blockIdx.x * 64;
    const int tid = threadIdx.x;
#pragma unroll
    for (int u = 0; u < 4; u++) {
        int idx = u * 256 + tid;
        int cc = idx >> 4, j4 = idx & 15;
        float4 v = *(const float4*)&x[((size_t)b * C_ + cb + cc) * NQ_ + nb + j4 * 4];
        Ts[(j4 * 4 + 0) * 65 + cc] = v.x;
        Ts[(j4 * 4 + 1) * 65 + cc] = v.y;
        Ts[(j4 * 4 + 2) * 65 + cc] = v.z;
        Ts[(j4 * 4 + 3) * 65 + cc] = v.w;
    }
    __syncthreads();
#pragma unroll
    for (int u = 0; u < 4; u++) {
        int idx = u * 256 + tid;
        int nn = idx >> 4, c4 = idx & 15;
        uint2 o;
        o.x = f2h2(Ts[nn * 65 + c4 * 4], Ts[nn * 65 + c4 * 4 + 1]);
        o.y = f2h2(Ts[nn * 65 + c4 * 4 + 2], Ts[nn * 65 + c4 * 4 + 3]);
        *(uint2*)&d_xT[((size_t)b * NQ_ + nb + nn) * C_ + cb + c4 * 4] = o;
    }
}

// ---------------------------------------------------------------------------
// Kernel A: theta conv fp16 (epilogue scaled by LOG2E). Same as R14.
// ---------------------------------------------------------------------------
__global__ void __launch_bounds__(256, 2) conv_theta_kernel(const float* __restrict__ tb) {
    extern __shared__ unsigned short smh[];
    const int b = blockIdx.y;
    const int nbase = blockIdx.x * 64;
    const int tid = threadIdx.x;
    const int warp = tid >> 5, lane = tid & 31;
    const int g = lane >> 2, q4 = lane & 3;
    const int m0 = (warp >> 2) * 32;
    const int n0 = (warp & 3) * 32;
    const uint32_t smb = (uint32_t)__cvta_generic_to_shared(smh);
    const uint32_t XB[2] = {0u, 4608u}, WB[2] = {9216u, 18432u};
    const int fOff = FRAG_OFF(72);

    float acc[2][4][4];
#pragma unroll
    for (int i = 0; i < 2; i++)
#pragma unroll
        for (int j = 0; j < 4; j++)
#pragma unroll
            for (int k = 0; k < 4; k++) acc[i][j][k] = 0.f;

    const unsigned short* xb = d_xT + ((size_t)b * NQ_ + nbase) * C_;

#pragma unroll
    for (int u = 0; u < 2; u++) {
        int idx = u * 256 + tid;
        int r = idx >> 3, c8 = idx & 7;
        cpa(smb + (XB[0] + r * 72 + c8 * 8) * 2u, xb + (size_t)r * C_ + c8 * 8);
    }
#pragma unroll
    for (int u = 0; u < 4; u++) {
        int idx = u * 256 + tid;
        int r = idx >> 3, c8 = idx & 7;
        cpa(smb + (WB[0] + r * 72 + c8 * 8) * 2u, &twr[r * C_ + c8 * 8]);
    }
    CP_COMMIT();

    for (int ch = 0; ch < 4; ch++) {
        CP_WAIT0();
        __syncthreads();
        if (ch < 3) {
            int c0 = (ch + 1) * 64, buf = (ch + 1) & 1;
#pragma unroll
            for (int u = 0; u < 2; u++) {
                int idx = u * 256 + tid;
                int r = idx >> 3, c8 = idx & 7;
                cpa(smb + (XB[buf] + r * 72 + c8 * 8) * 2u, xb + (size_t)r * C_ + c0 + c8 * 8);
            }
#pragma unroll
            for (int u = 0; u < 4; u++) {
                int idx = u * 256 + tid;
                int r = idx >> 3, c8 = idx & 7;
                cpa(smb + (WB[buf] + r * 72 + c8 * 8) * 2u, &twr[r * C_ + c0 + c8 * 8]);
            }
            CP_COMMIT();
        }
#pragma unroll
        for (int ks = 0; ks < 4; ks++) {
            uint32_t a[2][4];
#pragma unroll
            for (int mt = 0; mt < 2; mt++)
                ldsm_x4(a[mt], smb + (uint32_t)(XB[ch & 1] + (m0 + mt * 16) * 72
                                                + ks * 16 + fOff) * 2u);
#pragma unroll
            for (int np = 0; np < 2; np++) {
                uint32_t bb[4];
                ldsm_x4(bb, smb + (uint32_t)(WB[ch & 1] + (n0 + np * 16) * 72
                                             + ks * 16 + fOff) * 2u);
#pragma unroll
                for (int mt = 0; mt < 2; mt++) {
                    mma_f16(acc[mt][2 * np], a[mt], bb[0], bb[2]);
                    mma_f16(acc[mt][2 * np + 1], a[mt], bb[1], bb[3]);
                }
            }
        }
    }
#pragma unroll
    for (int j = 0; j < 4; j++) {
        int o = n0 + j * 8 + 2 * q4;
        float b0 = tb[o], b1 = tb[o + 1];
#pragma unroll
        for (int mt = 0; mt < 2; mt++) {
            size_t r = (size_t)b * NQ_ + nbase + m0 + mt * 16 + g;
            *(uint32_t*)&d_theta[r * CI_ + o] =
                f2h2((acc[mt][j][0] + b0) * LOG2E, (acc[mt][j][1] + b1) * LOG2E);
            *(uint32_t*)&d_theta[(r + 8) * CI_ + o] =
                f2h2((acc[mt][j][2] + b0) * LOG2E, (acc[mt][j][3] + b1) * LOG2E);
        }
    }
}

// ---------------------------------------------------------------------------
// Kernel B: g/phi conv + maxpool fp16. Same as R14.
// ---------------------------------------------------------------------------
__global__ void __launch_bounds__(256, 2) conv_gphi_kernel(
        const float* __restrict__ gb, const float* __restrict__ pb) {
    extern __shared__ unsigned short smh[];
    const int b = blockIdx.z;
    const int ob = blockIdx.y;
    const int t = blockIdx.x >> 4, hp = blockIdx.x & 15;
    const int nbase = t * 1024 + hp * 64;
    const int tid = threadIdx.x;
    const int warp = tid >> 5, lane = tid & 31;
    const int g = lane >> 2, q4 = lane & 3;
    const int m0 = (warp >> 2) * 32;
    const int n0 = (warp & 3) * 16;
    const uint32_t smb = (uint32_t)__cvta_generic_to_shared(smh);
    const uint32_t XB[2] = {0u, 4608u}, GB[2] = {9216u, 13824u}, PB[2] = {18432u, 23040u};
    const int fOff = FRAG_OFF(72);

    float ag[2][2][4], ap[2][2][4];
#pragma unroll
    for (int i = 0; i < 2; i++)
#pragma unroll
        for (int j = 0; j < 2; j++)
#pragma unroll
            for (int k = 0; k < 4; k++) { ag[i][j][k] = 0.f; ap[i][j][k] = 0.f; }

    const unsigned short* xb = d_xT + ((size_t)b * NQ_ + nbase) * C_;
    const unsigned short* gwb = gwr + (ob * 64) * C_;
    const unsigned short* pwb = pwr + (ob * 64) * C_;

#pragma unroll
    for (int u = 0; u < 2; u++) {
        int idx = u * 256 + tid;
        int r = idx >> 3, c8 = idx & 7;
        cpa(smb + (XB[0] + r * 72 + c8 * 8) * 2u, xb + (size_t)r * C_ + c8 * 8);
        cpa(smb + (GB[0] + r * 72 + c8 * 8) * 2u, gwb + r * C_ + c8 * 8);
        cpa(smb + (PB[0] + r * 72 + c8 * 8) * 2u, pwb + r * C_ + c8 * 8);
    }
    CP_COMMIT();

    for (int ch = 0; ch < 4; ch++) {
        CP_WAIT0();
        __syncthreads();
        if (ch < 3) {
            int c0 = (ch + 1) * 64, buf = (ch + 1) & 1;
#pragma unroll
            for (int u = 0; u < 2; u++) {
                int idx = u * 256 + tid;
                int r = idx >> 3, c8 = idx & 7;
                cpa(smb + (XB[buf] + r * 72 + c8 * 8) * 2u, xb + (size_t)r * C_ + c0 + c8 * 8);
                cpa(smb + (GB[buf] + r * 72 + c8 * 8) * 2u, gwb + r * C_ + c0 + c8 * 8);
                cpa(smb + (PB[buf] + r * 72 + c8 * 8) * 2u, pwb + r * C_ + c0 + c8 * 8);
            }
            CP_COMMIT();
        }
#pragma unroll
        for (int ks = 0; ks < 4; ks++) {
            uint32_t a[2][4];
#pragma unroll
            for (int mt = 0; mt < 2; mt++)
                ldsm_x4(a[mt], smb + (uint32_t)(XB[ch & 1] + (m0 + mt * 16) * 72
                                                + ks * 16 + fOff) * 2u);
            uint32_t bg_[4], bp_[4];
            ldsm_x4(bg_, smb + (uint32_t)(GB[ch & 1] + n0 * 72 + ks * 16 + fOff) * 2u);
            ldsm_x4(bp_, smb + (uint32_t)(PB[ch & 1] + n0 * 72 + ks * 16 + fOff) * 2u);
#pragma unroll
            for (int mt = 0; mt < 2; mt++) {
                mma_f16(ag[mt][0], a[mt], bg_[0], bg_[2]);
                mma_f16(ag[mt][1], a[mt], bg_[1], bg_[3]);
                mma_f16(ap[mt][0], a[mt], bp_[0], bp_[2]);
                mma_f16(ap[mt][1], a[mt], bp_[1], bp_[3]);
            }
        }
    }
    __syncthreads();
    float* Sg = (float*)smh;            // [64][68]
    float* Sp = (float*)smh + 4352;     // [64][68]
    float* Pv = (float*)smh + 8704;     // [64][20]
#pragma unroll
    for (int mt = 0; mt < 2; mt++) {
#pragma unroll
        for (int j = 0; j < 2; j++) {
            int r = m0 + mt * 16 + g;
            int o = n0 + j * 8 + 2 * q4;
            *(float2*)&Sg[r * 68 + o] = *(float2*)&ag[mt][j][0];
            *(float2*)&Sg[(r + 8) * 68 + o] = *(float2*)&ag[mt][j][2];
            *(float2*)&Sp[r * 68 + o] = *(float2*)&ap[mt][j][0];
            *(float2*)&Sp[(r + 8) * 68 + o] = *(float2*)&ap[mt][j][2];
        }
    }
    __syncthreads();
    const int mb = t * 256 + hp * 16;
    {
        int p = tid >> 4, o4 = (tid & 15) * 4;
        float4 bgv = *(const float4*)&gb[ob * 64 + o4];
        float4 bpv = *(const float4*)&pb[ob * 64 + o4];
        float4 r0, r1, r2, r3;
        r0 = *(float4*)&Sp[(2 * p) * 68 + o4];
        r1 = *(float4*)&Sp[(2 * p + 1) * 68 + o4];
        r2 = *(float4*)&Sp[(32 + 2 * p) * 68 + o4];
        r3 = *(float4*)&Sp[(33 + 2 * p) * 68 + o4];
        uint2 ko;
        ko.x = f2h2(fmaxf(fmaxf(r0.x, r1.x), fmaxf(r2.x, r3.x)) + bpv.x,
                    fmaxf(fmaxf(r0.y, r1.y), fmaxf(r2.y, r3.y)) + bpv.y);
        ko.y = f2h2(fmaxf(fmaxf(r0.z, r1.z), fmaxf(r2.z, r3.z)) + bpv.z,
                    fmaxf(fmaxf(r0.w, r1.w), fmaxf(r2.w, r3.w)) + bpv.w);
        *(uint2*)&d_key[((size_t)b * NKV_ + mb + p) * CI_ + ob * 64 + o4] = ko;
        r0 = *(float4*)&Sg[(2 * p) * 68 + o4];
        r1 = *(float4*)&Sg[(2 * p + 1) * 68 + o4];
        r2 = *(float4*)&Sg[(32 + 2 * p) * 68 + o4];
        r3 = *(float4*)&Sg[(33 + 2 * p) * 68 + o4];
        Pv[(o4 + 0) * 20 + p] = fmaxf(fmaxf(r0.x, r1.x), fmaxf(r2.x, r3.x)) + bgv.x;
        Pv[(o4 + 1) * 20 + p] = fmaxf(fmaxf(r0.y, r1.y), fmaxf(r2.y, r3.y)) + bgv.y;
        Pv[(o4 + 2) * 20 + p] = fmaxf(fmaxf(r0.z, r1.z), fmaxf(r2.z, r3.z)) + bgv.z;
        Pv[(o4 + 3) * 20 + p] = fmaxf(fmaxf(r0.w, r1.w), fmaxf(r2.w, r3.w)) + bgv.w;
    }
    __syncthreads();
    {
        int ci = tid >> 2, j = (tid & 3) * 4;
        uint2 v;
        v.x = f2h2(Pv[ci * 20 + j], Pv[ci * 20 + j + 1]);
        v.y = f2h2(Pv[ci * 20 + j + 2], Pv[ci * 20 + j + 3]);
        *(uint2*)&d_valT[((size_t)b * CI_ + ob * 64 + ci) * NKV_ + mb + j] = v;
    }
}

// ---------------------------------------------------------------------------
// Kernel C: fp16 flash attention, 2 blocks/SM. Q resident in smem (fragments
// reloaded per k-step), R14 numerics otherwise.
// smem halves: Q@0 [128][136]=17408; K0@17408 K1@26112 ([64][136]);
//   V0@34816 V1@44032 ([128][72]). total 53248 h = 106496 B (x2 = 208 KB/SM).
// ---------------------------------------------------------------------------
__global__ void __launch_bounds__(256, 2) attn_kernel() {
    extern __shared__ unsigned short smh[];
    const int b = blockIdx.y;
    const int qbase = blockIdx.x * 128;
    const int tid = threadIdx.x;
    const int warp = tid >> 5, lane = tid & 31;
    const int g = lane >> 2, q4 = lane & 3;
    const int r0 = warp * 16 + g;
    const uint32_t smb = (uint32_t)__cvta_generic_to_shared(smh);
    const uint32_t QB = 0u, KB0 = 17408u, KB1 = 26112u, VB0 = 34816u, VB1 = 44032u;

    const unsigned short* qb = d_theta + ((size_t)b * NQ_ + qbase) * CI_;
    const unsigned short* keyb = d_key + (size_t)b * NKV_ * CI_;
    const unsigned short* valb = d_valT + (size_t)b * CI_ * NKV_;

    // hoisted per-thread copy offsets (loop-invariant)
    int kgo[4], kso[4], vgo[4], vso[4];
#pragma unroll
    for (int u = 0; u < 4; u++) {
        int idx = u * 256 + tid;
        int rk = idx >> 4, ck = idx & 15;
        kgo[u] = rk * CI_ + ck * 8;
        kso[u] = (rk * 136 + ck * 8) * 2;
        int rv = idx >> 3, cv = idx & 7;
        vgo[u] = rv * NKV_ + cv * 8;
        vso[u] = (rv * 72 + cv * 8) * 2;
    }

    // prologue: Q + K0 + V0, single group
#pragma unroll
    for (int u = 0; u < 8; u++) {
        int idx = u * 256 + tid;
        int r = idx >> 4, c8 = idx & 15;
        cpa(smb + (QB + r * 136 + c8 * 8) * 2u, qb + (size_t)r * CI_ + c8 * 8);
    }
#pragma unroll
    for (int u = 0; u < 4; u++) {
        cpa(smb + KB0 * 2u + kso[u], keyb + kgo[u]);
        cpa(smb + VB0 * 2u + vso[u], valb + vgo[u]);
    }
    CP_COMMIT();

    // hoisted LDSM lane bases (byte addresses)
    const uint32_t qA = smb + (uint32_t)(QB + warp * 16 * 136
                                         + (lane & 15) * 136 + (lane >> 4) * 8) * 2u;
    const uint32_t kA[2] = {smb + KB0 * 2u + (uint32_t)FRAG_OFF(136) * 2u,
                            smb + KB1 * 2u + (uint32_t)FRAG_OFF(136) * 2u};
    const uint32_t vA[2] = {smb + VB0 * 2u + (uint32_t)FRAG_OFF(72) * 2u,
                            smb + VB1 * 2u + (uint32_t)FRAG_OFF(72) * 2u};
    const uint32_t kS[2] = {smb + KB0 * 2u, smb + KB1 * 2u};
    const uint32_t vS[2] = {smb + VB0 * 2u, smb + VB1 * 2u};

    float m[2] = {-3.0e38f, -3.0e38f}, l[2] = {0.f, 0.f};
    float oacc[16][4];
#pragma unroll
    for (int i = 0; i < 16; i++)
#pragma unroll
        for (int j = 0; j < 4; j++) oacc[i][j] = 0.f;

    for (int it = 0; it < 16; it++) {
#pragma unroll
        for (int hb = 0; hb < 2; hb++) {
            const int mt = it * 2 + hb;
            CP_WAIT0();
            __syncthreads();
            if (mt + 1 < 32) {
                const int nb = (mt + 1) * 64;
                const unsigned short* ksrc = keyb + (size_t)nb * CI_;
                const unsigned short* vsrc = valb + nb;
#pragma unroll
                for (int u = 0; u < 4; u++)
                    cpa(kS[hb ^ 1] + kso[u], ksrc + kgo[u]);
#pragma unroll
                for (int u = 0; u < 4; u++)
                    cpa(vS[hb ^ 1] + vso[u], vsrc + vgo[u]);
                CP_COMMIT();
            }

            // S = Q K^T (log2 units): Q fragment reloaded per k-step
            float sacc[8][4];
#pragma unroll
            for (int i = 0; i < 8; i++)
#pragma unroll
                for (int j = 0; j < 4; j++) sacc[i][j] = 0.f;
#pragma unroll
            for (int ks = 0; ks < 8; ks++) {
                uint32_t qf[4];
                ldsm_x4(qf, qA + (uint32_t)(ks * 16) * 2u);
#pragma unroll
                for (int np = 0; np < 4; np++) {
                    uint32_t bb[4];
                    ldsm_x4(bb, kA[hb] + (uint32_t)(np * 16 * 136 + ks * 16) * 2u);
                    mma_f16(sacc[2 * np], qf, bb[0], bb[2]);
                    mma_f16(sacc[2 * np + 1], qf, bb[1], bb[3]);
                }
            }

            // online softmax; rescale only when row max rises
#pragma unroll
            for (int h = 0; h < 2; h++) {
                float tmax = -3.0e38f;
#pragma unroll
                for (int nt = 0; nt < 8; nt++)
                    tmax = fmaxf(tmax, fmaxf(sacc[nt][2 * h], sacc[nt][2 * h + 1]));
                tmax = fmaxf(tmax, __shfl_xor_sync(0xffffffffu, tmax, 1));
                tmax = fmaxf(tmax, __shfl_xor_sync(0xffffffffu, tmax, 2));
                if (tmax > m[h]) {
                    float fac = exp2f(m[h] - tmax);
                    m[h] = tmax;
                    l[h] *= fac;
#pragma unroll
                    for (int ot = 0; ot < 16; ot++) {
                        oacc[ot][2 * h]     *= fac;
                        oacc[ot][2 * h + 1] *= fac;
                    }
                }
            }

#pragma unroll
            for (int nt = 0; nt < 8; nt++) {
                float e0 = exp2f(sacc[nt][0] - m[0]);
                float e1 = exp2f(sacc[nt][1] - m[0]);
                float e2 = exp2f(sacc[nt][2] - m[1]);
                float e3 = exp2f(sacc[nt][3] - m[1]);
                l[0] += e0 + e1;
                l[1] += e2 + e3;
                sacc[nt][0] = e0; sacc[nt][1] = e1;
                sacc[nt][2] = e2; sacc[nt][3] = e3;
            }

            // O += P V : P fragments straight from registers
#pragma unroll
            for (int ks = 0; ks < 4; ks++) {
                uint32_t a[4];
                a[0] = f2h2(sacc[2 * ks][0], sacc[2 * ks][1]);
                a[1] = f2h2(sacc[2 * ks][2], sacc[2 * ks][3]);
                a[2] = f2h2(sacc[2 * ks + 1][0], sacc[2 * ks + 1][1]);
                a[3] = f2h2(sacc[2 * ks + 1][2], sacc[2 * ks + 1][3]);
#pragma unroll
                for (int np = 0; np < 8; np++) {
                    uint32_t bb[4];
                    ldsm_x4(bb, vA[hb] + (uint32_t)(np * 16 * 72 + ks * 16) * 2u);
                    mma_f16(oacc[2 * np], a, bb[0], bb[2]);
                    mma_f16(oacc[2 * np + 1], a, bb[1], bb[3]);
                }
            }
        }
    }

    // deferred l lane-reduction, normalize, write
#pragma unroll
    for (int h = 0; h < 2; h++) {
        l[h] += __shfl_xor_sync(0xffffffffu, l[h], 1);
        l[h] += __shfl_xor_sync(0xffffffffu, l[h], 2);
    }
    float inv0 = 1.f / l[0], inv1 = 1.f / l[1];
    size_t row0 = (size_t)b * NQ_ + qbase + r0;
#pragma unroll
    for (int nt = 0; nt < 16; nt++) {
        int ci = nt * 8 + 2 * q4;
        *(uint32_t*)&d_yy[row0 * CI_ + ci] = f2h2(oacc[nt][0] * inv0, oacc[nt][1] * inv0);
        *(uint32_t*)&d_yy[(row0 + 8) * CI_ + ci] = f2h2(oacc[nt][2] * inv1, oacc[nt][3] * inv1);
    }
}

// ---------------------------------------------------------------------------
// Kernel D: wconv + BN + residual fp16. Same as R14.
// ---------------------------------------------------------------------------
__global__ void __launch_bounds__(256, 2) wconv_kernel(
        const float* __restrict__ x,
        const float* __restrict__ wb,
        const float* __restrict__ bng, const float* __restrict__ bnb,
        const float* __restrict__ bnm, const float* __restrict__ bnv,
        float* __restrict__ out) {
    extern __shared__ unsigned short smh[];
    const int b = blockIdx.z;
    const int cobase = blockIdx.y * 128;
    const int nbase = blockIdx.x * 64;
    const int tid = threadIdx.x;
    const int warp = tid >> 5, lane = tid & 31;
    const int g = lane >> 2, q4 = lane & 3;
    const int m0 = (warp >> 1) * 32;
    const int n0 = (warp & 1) * 32;
    const uint32_t smb = (uint32_t)__cvta_generic_to_shared(smh);
    const uint32_t WB[2] = {0u, 9216u}, YB[2] = {18432u, 23040u};
    const int fOff = FRAG_OFF(72);

    float acc[2][4][4];
#pragma unroll
    for (int i = 0; i < 2; i++)
#pragma unroll
        for (int j = 0; j < 4; j++)
#pragma unroll
            for (int k = 0; k < 4; k++) acc[i][j][k] = 0.f;

    const unsigned short* yb = d_yy + ((size_t)b * NQ_ + nbase) * CI_;

#pragma unroll
    for (int u = 0; u < 4; u++) {
        int idx = u * 256 + tid;
        int r = idx >> 3, c8 = idx & 7;
        cpa(smb + (WB[0] + r * 72 + c8 * 8) * 2u, &wwr[(cobase + r) * CI_ + c8 * 8]);
    }
#pragma unroll
    for (int u = 0; u < 2; u++) {
        int idx = u * 256 + tid;
        int r = idx >> 3, c8 = idx & 7;
        cpa(smb + (YB[0] + r * 72 + c8 * 8) * 2u, yb + (size_t)r * CI_ + c8 * 8);
    }
    CP_COMMIT();

    for (int ch = 0; ch < 2; ch++) {
        CP_WAIT0();
        __syncthreads();
        if (ch < 1) {
#pragma unroll
            for (int u = 0; u < 4; u++) {
                int idx = u * 256 + tid;
                int r = idx >> 3, c8 = idx & 7;
                cpa(smb + (WB[1] + r * 72 + c8 * 8) * 2u,
                    &wwr[(cobase + r) * CI_ + 64 + c8 * 8]);
            }
#pragma unroll
            for (int u = 0; u < 2; u++) {
                int idx = u * 256 + tid;
                int r = idx >> 3, c8 = idx & 7;
                cpa(smb + (YB[1] + r * 72 + c8 * 8) * 2u,
                    yb + (size_t)r * CI_ + 64 + c8 * 8);
            }
            CP_COMMIT();
        }
#pragma unroll
        for (int ks = 0; ks < 4; ks++) {
            uint32_t a[2][4];
#pragma unroll
            for (int mt = 0; mt < 2; mt++)
                ldsm_x4(a[mt], smb + (uint32_t)(WB[ch & 1] + (m0 + mt * 16) * 72
                                                + ks * 16 + fOff) * 2u);
#pragma unroll
            for (int np = 0; np < 2; np++) {
                uint32_t bb[4];
                ldsm_x4(bb, smb + (uint32_t)(YB[ch & 1] + (n0 + np * 16) * 72
                                             + ks * 16 + fOff) * 2u);
#pragma unroll
                for (int mt = 0; mt < 2; mt++) {
                    mma_f16(acc[mt][2 * np], a[mt], bb[0], bb[2]);
                    mma_f16(acc[mt][2 * np + 1], a[mt], bb[1], bb[3]);
                }
            }
        }
    }

    float sc[2][2], sh[2][2];
#pragma unroll
    for (int mt = 0; mt < 2; mt++)
#pragma unroll
        for (int h = 0; h < 2; h++) {
            int co = cobase + m0 + mt * 16 + g + h * 8;
            float s = bng[co] * rsqrtf(bnv[co] + 1e-5f);
            sc[mt][h] = s;
            sh[mt][h] = bnb[co] - bnm[co] * s + s * wb[co];
        }
#pragma unroll
    for (int mt = 0; mt < 2; mt++) {
#pragma unroll
        for (int j = 0; j < 4; j++) {
            int n = nbase + n0 + j * 8 + 2 * q4;
#pragma unroll
            for (int h = 0; h < 2; h++) {
                int co = cobase + m0 + mt * 16 + g + h * 8;
                size_t base = ((size_t)b * C_ + co) * NQ_ + n;
                float2 xv = *(const float2*)&x[base];
                float2 o;
                o.x = acc[mt][j][2 * h]     * sc[mt][h] + sh[mt][h] + xv.x;
                o.y = acc[mt][j][2 * h + 1] * sc[mt][h] + sh[mt][h] + xv.y;
                *(float2*)&out[base] = o;
            }
        }
    }
}

// ---------------------------------------------------------------------------
extern "C" void kernel_launch(void* const* d_in, const int* in_sizes, int n_in,
                              void* d_out, int out_size) {
    const float* x    = (const float*)d_in[0];
    const float* g_w  = (const float*)d_in[1];
    const float* g_b  = (const float*)d_in[2];
    const float* th_w = (const float*)d_in[3];
    const float* th_b = (const float*)d_in[4];
    const float* ph_w = (const float*)d_in[5];
    const float* ph_b = (const float*)d_in[6];
    const float* w_w  = (const float*)d_in[7];
    const float* w_b  = (const float*)d_in[8];
    const float* bn_g = (const float*)d_in[9];
    const float* bn_b = (const float*)d_in[10];
    const float* bn_m = (const float*)d_in[11];
    const float* bn_v = (const float*)d_in[12];
    float* out = (float*)d_out;

    const int smA = 27648 * 2;   // 55296
    const int smB = 27648 * 2;   // 55296
    const int smC = 53248 * 2;   // 106496
    const int smD = 27648 * 2;   // 55296

    cudaFuncSetAttribute(conv_theta_kernel, cudaFuncAttributeMaxDynamicSharedMemorySize, smA);
    cudaFuncSetAttribute(conv_gphi_kernel,  cudaFuncAttributeMaxDynamicSharedMemorySize, smB);
    cudaFuncSetAttribute(attn_kernel,       cudaFuncAttributeMaxDynamicSharedMemorySize, smC);
    cudaFuncSetAttribute(wconv_kernel,      cudaFuncAttributeMaxDynamicSharedMemorySize, smD);

    prep_kernel<<<dim3(128, 4, 5), 256>>>(x, th_w, g_w, ph_w, w_w);
    conv_theta_kernel<<<dim3(NQ_ / 64, B_), 256, smA>>>(th_b);
    conv_gphi_kernel<<<dim3(128, 2, B_), 256, smB>>>(g_b, ph_b);
    attn_kernel<<<dim3(NQ_ / 128, B_), 256, smC>>>();
    wconv_kernel<<<dim3(NQ_ / 64, 2, B_), 256, smD>>>(x, w_b,
                                                      bn_g, bn_b, bn_m, bn_v, out);
}

// round 17
// speedup vs baseline: 2.1849x; 1.0373x over previous
#include <cuda_runtime.h>
#include <cuda_fp16.h>
#include <math.h>
#include <stdint.h>

#define B_  4
#define C_  256
#define CI_ 128
#define NQ_ 8192
#define NKV_ 2048
#define LOG2E 1.44269504f

// scratch (no cudaMalloc allowed) — all fp16 payloads stored as u16
__device__ unsigned short d_xT  [(size_t)B_ * NQ_ * C_];   // (b, n, c)
__device__ unsigned short twr   [CI_ * C_];
__device__ unsigned short gwr   [CI_ * C_];
__device__ unsigned short pwr   [CI_ * C_];
__device__ unsigned short wwr   [C_ * CI_];
__device__ unsigned short d_theta[(size_t)B_ * NQ_ * CI_]; // (b, n, ci) pre-scaled by log2e
__device__ unsigned short d_key  [(size_t)B_ * NKV_ * CI_];// (b, m, ci)
__device__ unsigned short d_valT [(size_t)B_ * CI_ * NKV_];// (b, ci, m)
__device__ unsigned short d_yy   [(size_t)B_ * NQ_ * CI_]; // (b, n, ci)

__device__ __forceinline__ uint32_t f2h2(float lo, float hi) {
    uint32_t r;
    asm("cvt.rn.f16x2.f32 %0, %1, %2;" : "=r"(r) : "f"(hi), "f"(lo));
    return r;
}

__device__ __forceinline__ uint32_t h2exp2(uint32_t x) {
    uint32_t r;
    asm("ex2.approx.f16x2 %0, %1;" : "=r"(r) : "r"(x));
    return r;
}

__device__ __forceinline__ void mma_f16(float* c, const uint32_t* a,
                                        uint32_t b0, uint32_t b1) {
    asm volatile(
        "mma.sync.aligned.m16n8k16.row.col.f32.f16.f16.f32 "
        "{%0,%1,%2,%3}, {%4,%5,%6,%7}, {%8,%9}, {%0,%1,%2,%3};"
        : "+f"(c[0]), "+f"(c[1]), "+f"(c[2]), "+f"(c[3])
        : "r"(a[0]), "r"(a[1]), "r"(a[2]), "r"(a[3]), "r"(b0), "r"(b1));
}

__device__ __forceinline__ void ldsm_x4(uint32_t* r, uint32_t a) {
    asm volatile("ldmatrix.sync.aligned.m8n8.x4.shared.b16 {%0,%1,%2,%3}, [%4];"
                 : "=r"(r[0]), "=r"(r[1]), "=r"(r[2]), "=r"(r[3]) : "r"(a));
}

__device__ __forceinline__ void cpa(uint32_t dst, const void* src) {
    asm volatile("cp.async.cg.shared.global [%0], [%1], 16;" :: "r"(dst), "l"(src));
}
#define CP_COMMIT() asm volatile("cp.async.commit_group;")
#define CP_WAIT0()  asm volatile("cp.async.wait_group 0;")

// fragment base offsets (in halves): row = lane&15, k-half = lane>>4
#define FRAG_OFF(stride) ((lane & 15) * (stride) + (lane >> 4) * 8)

// ---------------------------------------------------------------------------
// Prep: z<4 -> transpose+round x slice to fp16; z==4 -> round weights.
// ---------------------------------------------------------------------------
__global__ void __launch_bounds__(256) prep_kernel(
        const float* __restrict__ x,
        const float* __restrict__ tw, const float* __restrict__ gw,
        const float* __restrict__ pw, const float* __restrict__ ww) {
    if (blockIdx.z == 4) {
        int bid = blockIdx.y * 128 + blockIdx.x;
        if (bid >= 16) return;
        int i = (bid * 256 + threadIdx.x) * 8;
        float4 v0, v1;
        uint2 o;
        v0 = *(const float4*)&tw[i]; v1 = *(const float4*)&tw[i + 4];
        o.x = f2h2(v0.x, v0.y); o.y = f2h2(v0.z, v0.w);
        *(uint2*)&twr[i] = o;
        o.x = f2h2(v1.x, v1.y); o.y = f2h2(v1.z, v1.w);
        *(uint2*)&twr[i + 4] = o;
        v0 = *(const float4*)&gw[i]; v1 = *(const float4*)&gw[i + 4];
        o.x = f2h2(v0.x, v0.y); o.y = f2h2(v0.z, v0.w);
        *(uint2*)&gwr[i] = o;
        o.x = f2h2(v1.x, v1.y); o.y = f2h2(v1.z, v1.w);
        *(uint2*)&gwr[i + 4] = o;
        v0 = *(const float4*)&pw[i]; v1 = *(const float4*)&pw[i + 4];
        o.x = f2h2(v0.x, v0.y); o.y = f2h2(v0.z, v0.w);
        *(uint2*)&pwr[i] = o;
        o.x = f2h2(v1.x, v1.y); o.y = f2h2(v1.z, v1.w);
        *(uint2*)&pwr[i + 4] = o;
        v0 = *(const float4*)&ww[i]; v1 = *(const float4*)&ww[i + 4];
        o.x = f2h2(v0.x, v0.y); o.y = f2h2(v0.z, v0.w);
        *(uint2*)&wwr[i] = o;
        o.x = f2h2(v1.x, v1.y); o.y = f2h2(v1.z, v1.w);
        *(uint2*)&wwr[i + 4] = o;
        return;
    }
    __shared__ float Ts[64 * 65];
    const int b = blockIdx.z, cb = blockIdx.y * 64, nb = blockIdx.x * 64;
    const int tid = threadIdx.x;
#pragma unroll
    for (int u = 0; u < 4; u++) {
        int idx = u * 256 + tid;
        int cc = idx >> 4, j4 = idx & 15;
        float4 v = *(const float4*)&x[((size_t)b * C_ + cb + cc) * NQ_ + nb + j4 * 4];
        Ts[(j4 * 4 + 0) * 65 + cc] = v.x;
        Ts[(j4 * 4 + 1) * 65 + cc] = v.y;
        Ts[(j4 * 4 + 2) * 65 + cc] = v.z;
        Ts[(j4 * 4 + 3) * 65 + cc] = v.w;
    }
    __syncthreads();
#pragma unroll
    for (int u = 0; u < 4; u++) {
        int idx = u * 256 + tid;
        int nn = idx >> 4, c4 = idx & 15;
        uint2 o;
        o.x = f2h2(Ts[nn * 65 + c4 * 4], Ts[nn * 65 + c4 * 4 + 1]);
        o.y = f2h2(Ts[nn * 65 + c4 * 4 + 2], Ts[nn * 65 + c4 * 4 + 3]);
        *(uint2*)&d_xT[((size_t)b * NQ_ + nb + nn) * C_ + cb + c4 * 4] = o;
    }
}

// ---------------------------------------------------------------------------
// Kernel A: theta conv fp16 (epilogue scaled by LOG2E). Same as R15.
// ---------------------------------------------------------------------------
__global__ void __launch_bounds__(256, 2) conv_theta_kernel(const float* __restrict__ tb) {
    extern __shared__ unsigned short smh[];
    const int b = blockIdx.y;
    const int nbase = blockIdx.x * 64;
    const int tid = threadIdx.x;
    const int warp = tid >> 5, lane = tid & 31;
    const int g = lane >> 2, q4 = lane & 3;
    const int m0 = (warp >> 2) * 32;
    const int n0 = (warp & 3) * 32;
    const uint32_t smb = (uint32_t)__cvta_generic_to_shared(smh);
    const uint32_t XB[2] = {0u, 4608u}, WB[2] = {9216u, 18432u};
    const int fOff = FRAG_OFF(72);

    float acc[2][4][4];
#pragma unroll
    for (int i = 0; i < 2; i++)
#pragma unroll
        for (int j = 0; j < 4; j++)
#pragma unroll
            for (int k = 0; k < 4; k++) acc[i][j][k] = 0.f;

    const unsigned short* xb = d_xT + ((size_t)b * NQ_ + nbase) * C_;

#pragma unroll
    for (int u = 0; u < 2; u++) {
        int idx = u * 256 + tid;
        int r = idx >> 3, c8 = idx & 7;
        cpa(smb + (XB[0] + r * 72 + c8 * 8) * 2u, xb + (size_t)r * C_ + c8 * 8);
    }
#pragma unroll
    for (int u = 0; u < 4; u++) {
        int idx = u * 256 + tid;
        int r = idx >> 3, c8 = idx & 7;
        cpa(smb + (WB[0] + r * 72 + c8 * 8) * 2u, &twr[r * C_ + c8 * 8]);
    }
    CP_COMMIT();

    for (int ch = 0; ch < 4; ch++) {
        CP_WAIT0();
        __syncthreads();
        if (ch < 3) {
            int c0 = (ch + 1) * 64, buf = (ch + 1) & 1;
#pragma unroll
            for (int u = 0; u < 2; u++) {
                int idx = u * 256 + tid;
                int r = idx >> 3, c8 = idx & 7;
                cpa(smb + (XB[buf] + r * 72 + c8 * 8) * 2u, xb + (size_t)r * C_ + c0 + c8 * 8);
            }
#pragma unroll
            for (int u = 0; u < 4; u++) {
                int idx = u * 256 + tid;
                int r = idx >> 3, c8 = idx & 7;
                cpa(smb + (WB[buf] + r * 72 + c8 * 8) * 2u, &twr[r * C_ + c0 + c8 * 8]);
            }
            CP_COMMIT();
        }
#pragma unroll
        for (int ks = 0; ks < 4; ks++) {
            uint32_t a[2][4];
#pragma unroll
            for (int mt = 0; mt < 2; mt++)
                ldsm_x4(a[mt], smb + (uint32_t)(XB[ch & 1] + (m0 + mt * 16) * 72
                                                + ks * 16 + fOff) * 2u);
#pragma unroll
            for (int np = 0; np < 2; np++) {
                uint32_t bb[4];
                ldsm_x4(bb, smb + (uint32_t)(WB[ch & 1] + (n0 + np * 16) * 72
                                             + ks * 16 + fOff) * 2u);
#pragma unroll
                for (int mt = 0; mt < 2; mt++) {
                    mma_f16(acc[mt][2 * np], a[mt], bb[0], bb[2]);
                    mma_f16(acc[mt][2 * np + 1], a[mt], bb[1], bb[3]);
                }
            }
        }
    }
#pragma unroll
    for (int j = 0; j < 4; j++) {
        int o = n0 + j * 8 + 2 * q4;
        float b0 = tb[o], b1 = tb[o + 1];
#pragma unroll
        for (int mt = 0; mt < 2; mt++) {
            size_t r = (size_t)b * NQ_ + nbase + m0 + mt * 16 + g;
            *(uint32_t*)&d_theta[r * CI_ + o] =
                f2h2((acc[mt][j][0] + b0) * LOG2E, (acc[mt][j][1] + b1) * LOG2E);
            *(uint32_t*)&d_theta[(r + 8) * CI_ + o] =
                f2h2((acc[mt][j][2] + b0) * LOG2E, (acc[mt][j][3] + b1) * LOG2E);
        }
    }
}

// ---------------------------------------------------------------------------
// Kernel B: g/phi conv + maxpool fp16. Same as R15.
// ---------------------------------------------------------------------------
__global__ void __launch_bounds__(256, 2) conv_gphi_kernel(
        const float* __restrict__ gb, const float* __restrict__ pb) {
    extern __shared__ unsigned short smh[];
    const int b = blockIdx.z;
    const int ob = blockIdx.y;
    const int t = blockIdx.x >> 4, hp = blockIdx.x & 15;
    const int nbase = t * 1024 + hp * 64;
    const int tid = threadIdx.x;
    const int warp = tid >> 5, lane = tid & 31;
    const int g = lane >> 2, q4 = lane & 3;
    const int m0 = (warp >> 2) * 32;
    const int n0 = (warp & 3) * 16;
    const uint32_t smb = (uint32_t)__cvta_generic_to_shared(smh);
    const uint32_t XB[2] = {0u, 4608u}, GB[2] = {9216u, 13824u}, PB[2] = {18432u, 23040u};
    const int fOff = FRAG_OFF(72);

    float ag[2][2][4], ap[2][2][4];
#pragma unroll
    for (int i = 0; i < 2; i++)
#pragma unroll
        for (int j = 0; j < 2; j++)
#pragma unroll
            for (int k = 0; k < 4; k++) { ag[i][j][k] = 0.f; ap[i][j][k] = 0.f; }

    const unsigned short* xb = d_xT + ((size_t)b * NQ_ + nbase) * C_;
    const unsigned short* gwb = gwr + (ob * 64) * C_;
    const unsigned short* pwb = pwr + (ob * 64) * C_;

#pragma unroll
    for (int u = 0; u < 2; u++) {
        int idx = u * 256 + tid;
        int r = idx >> 3, c8 = idx & 7;
        cpa(smb + (XB[0] + r * 72 + c8 * 8) * 2u, xb + (size_t)r * C_ + c8 * 8);
        cpa(smb + (GB[0] + r * 72 + c8 * 8) * 2u, gwb + r * C_ + c8 * 8);
        cpa(smb + (PB[0] + r * 72 + c8 * 8) * 2u, pwb + r * C_ + c8 * 8);
    }
    CP_COMMIT();

    for (int ch = 0; ch < 4; ch++) {
        CP_WAIT0();
        __syncthreads();
        if (ch < 3) {
            int c0 = (ch + 1) * 64, buf = (ch + 1) & 1;
#pragma unroll
            for (int u = 0; u < 2; u++) {
                int idx = u * 256 + tid;
                int r = idx >> 3, c8 = idx & 7;
                cpa(smb + (XB[buf] + r * 72 + c8 * 8) * 2u, xb + (size_t)r * C_ + c0 + c8 * 8);
                cpa(smb + (GB[buf] + r * 72 + c8 * 8) * 2u, gwb + r * C_ + c0 + c8 * 8);
                cpa(smb + (PB[buf] + r * 72 + c8 * 8) * 2u, pwb + r * C_ + c0 + c8 * 8);
            }
            CP_COMMIT();
        }
#pragma unroll
        for (int ks = 0; ks < 4; ks++) {
            uint32_t a[2][4];
#pragma unroll
            for (int mt = 0; mt < 2; mt++)
                ldsm_x4(a[mt], smb + (uint32_t)(XB[ch & 1] + (m0 + mt * 16) * 72
                                                + ks * 16 + fOff) * 2u);
            uint32_t bg_[4], bp_[4];
            ldsm_x4(bg_, smb + (uint32_t)(GB[ch & 1] + n0 * 72 + ks * 16 + fOff) * 2u);
            ldsm_x4(bp_, smb + (uint32_t)(PB[ch & 1] + n0 * 72 + ks * 16 + fOff) * 2u);
#pragma unroll
            for (int mt = 0; mt < 2; mt++) {
                mma_f16(ag[mt][0], a[mt], bg_[0], bg_[2]);
                mma_f16(ag[mt][1], a[mt], bg_[1], bg_[3]);
                mma_f16(ap[mt][0], a[mt], bp_[0], bp_[2]);
                mma_f16(ap[mt][1], a[mt], bp_[1], bp_[3]);
            }
        }
    }
    __syncthreads();
    float* Sg = (float*)smh;            // [64][68]
    float* Sp = (float*)smh + 4352;     // [64][68]
    float* Pv = (float*)smh + 8704;     // [64][20]
#pragma unroll
    for (int mt = 0; mt < 2; mt++) {
#pragma unroll
        for (int j = 0; j < 2; j++) {
            int r = m0 + mt * 16 + g;
            int o = n0 + j * 8 + 2 * q4;
            *(float2*)&Sg[r * 68 + o] = *(float2*)&ag[mt][j][0];
            *(float2*)&Sg[(r + 8) * 68 + o] = *(float2*)&ag[mt][j][2];
            *(float2*)&Sp[r * 68 + o] = *(float2*)&ap[mt][j][0];
            *(float2*)&Sp[(r + 8) * 68 + o] = *(float2*)&ap[mt][j][2];
        }
    }
    __syncthreads();
    const int mb = t * 256 + hp * 16;
    {
        int p = tid >> 4, o4 = (tid & 15) * 4;
        float4 bgv = *(const float4*)&gb[ob * 64 + o4];
        float4 bpv = *(const float4*)&pb[ob * 64 + o4];
        float4 r0, r1, r2, r3;
        r0 = *(float4*)&Sp[(2 * p) * 68 + o4];
        r1 = *(float4*)&Sp[(2 * p + 1) * 68 + o4];
        r2 = *(float4*)&Sp[(32 + 2 * p) * 68 + o4];
        r3 = *(float4*)&Sp[(33 + 2 * p) * 68 + o4];
        uint2 ko;
        ko.x = f2h2(fmaxf(fmaxf(r0.x, r1.x), fmaxf(r2.x, r3.x)) + bpv.x,
                    fmaxf(fmaxf(r0.y, r1.y), fmaxf(r2.y, r3.y)) + bpv.y);
        ko.y = f2h2(fmaxf(fmaxf(r0.z, r1.z), fmaxf(r2.z, r3.z)) + bpv.z,
                    fmaxf(fmaxf(r0.w, r1.w), fmaxf(r2.w, r3.w)) + bpv.w);
        *(uint2*)&d_key[((size_t)b * NKV_ + mb + p) * CI_ + ob * 64 + o4] = ko;
        r0 = *(float4*)&Sg[(2 * p) * 68 + o4];
        r1 = *(float4*)&Sg[(2 * p + 1) * 68 + o4];
        r2 = *(float4*)&Sg[(32 + 2 * p) * 68 + o4];
        r3 = *(float4*)&Sg[(33 + 2 * p) * 68 + o4];
        Pv[(o4 + 0) * 20 + p] = fmaxf(fmaxf(r0.x, r1.x), fmaxf(r2.x, r3.x)) + bgv.x;
        Pv[(o4 + 1) * 20 + p] = fmaxf(fmaxf(r0.y, r1.y), fmaxf(r2.y, r3.y)) + bgv.y;
        Pv[(o4 + 2) * 20 + p] = fmaxf(fmaxf(r0.z, r1.z), fmaxf(r2.z, r3.z)) + bgv.z;
        Pv[(o4 + 3) * 20 + p] = fmaxf(fmaxf(r0.w, r1.w), fmaxf(r2.w, r3.w)) + bgv.w;
    }
    __syncthreads();
    {
        int ci = tid >> 2, j = (tid & 3) * 4;
        uint2 v;
        v.x = f2h2(Pv[ci * 20 + j], Pv[ci * 20 + j + 1]);
        v.y = f2h2(Pv[ci * 20 + j + 2], Pv[ci * 20 + j + 3]);
        *(uint2*)&d_valT[((size_t)b * CI_ + ob * 64 + ci) * NKV_ + mb + j] = v;
    }
}

// ---------------------------------------------------------------------------
// Kernel C: fp16 flash attention, 2 blocks/SM. Q in smem. f16x2 exp +
// ones-MMA row-sum l (no FADD lsum, no epilogue shuffles).
// smem halves: Q@0 [128][136]; K0@17408 K1@26112 ([64][136]);
//   V0@34816 V1@44032 ([128][72]). total 53248 h = 106496 B.
// ---------------------------------------------------------------------------
__global__ void __launch_bounds__(256, 2) attn_kernel() {
    extern __shared__ unsigned short smh[];
    const int b = blockIdx.y;
    const int qbase = blockIdx.x * 128;
    const int tid = threadIdx.x;
    const int warp = tid >> 5, lane = tid & 31;
    const int g = lane >> 2, q4 = lane & 3;
    const int r0 = warp * 16 + g;
    const uint32_t smb = (uint32_t)__cvta_generic_to_shared(smh);
    const uint32_t QB = 0u, KB0 = 17408u, KB1 = 26112u, VB0 = 34816u, VB1 = 44032u;
    const uint32_t ONES = 0x3C003C00u;   // half2(1.0, 1.0)

    const unsigned short* qb = d_theta + ((size_t)b * NQ_ + qbase) * CI_;
    const unsigned short* keyb = d_key + (size_t)b * NKV_ * CI_;
    const unsigned short* valb = d_valT + (size_t)b * CI_ * NKV_;

    int kgo[4], kso[4], vgo[4], vso[4];
#pragma unroll
    for (int u = 0; u < 4; u++) {
        int idx = u * 256 + tid;
        int rk = idx >> 4, ck = idx & 15;
        kgo[u] = rk * CI_ + ck * 8;
        kso[u] = (rk * 136 + ck * 8) * 2;
        int rv = idx >> 3, cv = idx & 7;
        vgo[u] = rv * NKV_ + cv * 8;
        vso[u] = (rv * 72 + cv * 8) * 2;
    }

#pragma unroll
    for (int u = 0; u < 8; u++) {
        int idx = u * 256 + tid;
        int r = idx >> 4, c8 = idx & 15;
        cpa(smb + (QB + r * 136 + c8 * 8) * 2u, qb + (size_t)r * CI_ + c8 * 8);
    }
#pragma unroll
    for (int u = 0; u < 4; u++) {
        cpa(smb + KB0 * 2u + kso[u], keyb + kgo[u]);
        cpa(smb + VB0 * 2u + vso[u], valb + vgo[u]);
    }
    CP_COMMIT();

    const uint32_t qA = smb + (uint32_t)(QB + warp * 16 * 136
                                         + (lane & 15) * 136 + (lane >> 4) * 8) * 2u;
    const uint32_t kA[2] = {smb + KB0 * 2u + (uint32_t)FRAG_OFF(136) * 2u,
                            smb + KB1 * 2u + (uint32_t)FRAG_OFF(136) * 2u};
    const uint32_t vA[2] = {smb + VB0 * 2u + (uint32_t)FRAG_OFF(72) * 2u,
                            smb + VB1 * 2u + (uint32_t)FRAG_OFF(72) * 2u};
    const uint32_t kS[2] = {smb + KB0 * 2u, smb + KB1 * 2u};
    const uint32_t vS[2] = {smb + VB0 * 2u, smb + VB1 * 2u};

    float m[2] = {-3.0e38f, -3.0e38f};
    float lacc[4] = {0.f, 0.f, 0.f, 0.f};   // ones-MMA accumulator: rows g (c0,c1), g+8 (c2,c3)
    float oacc[16][4];
#pragma unroll
    for (int i = 0; i < 16; i++)
#pragma unroll
        for (int j = 0; j < 4; j++) oacc[i][j] = 0.f;

    for (int it = 0; it < 16; it++) {
#pragma unroll
        for (int hb = 0; hb < 2; hb++) {
            const int mt = it * 2 + hb;
            CP_WAIT0();
            __syncthreads();
            if (mt + 1 < 32) {
                const int nb = (mt + 1) * 64;
                const unsigned short* ksrc = keyb + (size_t)nb * CI_;
                const unsigned short* vsrc = valb + nb;
#pragma unroll
                for (int u = 0; u < 4; u++)
                    cpa(kS[hb ^ 1] + kso[u], ksrc + kgo[u]);
#pragma unroll
                for (int u = 0; u < 4; u++)
                    cpa(vS[hb ^ 1] + vso[u], vsrc + vgo[u]);
                CP_COMMIT();
            }

            // S = Q K^T (log2 units)
            float sacc[8][4];
#pragma unroll
            for (int i = 0; i < 8; i++)
#pragma unroll
                for (int j = 0; j < 4; j++) sacc[i][j] = 0.f;
#pragma unroll
            for (int ks = 0; ks < 8; ks++) {
                uint32_t qf[4];
                ldsm_x4(qf, qA + (uint32_t)(ks * 16) * 2u);
#pragma unroll
                for (int np = 0; np < 4; np++) {
                    uint32_t bb[4];
                    ldsm_x4(bb, kA[hb] + (uint32_t)(np * 16 * 136 + ks * 16) * 2u);
                    mma_f16(sacc[2 * np], qf, bb[0], bb[2]);
                    mma_f16(sacc[2 * np + 1], qf, bb[1], bb[3]);
                }
            }

            // online softmax; rescale (incl. lacc) only when row max rises
#pragma unroll
            for (int h = 0; h < 2; h++) {
                float tmax = -3.0e38f;
#pragma unroll
                for (int nt = 0; nt < 8; nt++)
                    tmax = fmaxf(tmax, fmaxf(sacc[nt][2 * h], sacc[nt][2 * h + 1]));
                tmax = fmaxf(tmax, __shfl_xor_sync(0xffffffffu, tmax, 1));
                tmax = fmaxf(tmax, __shfl_xor_sync(0xffffffffu, tmax, 2));
                if (tmax > m[h]) {
                    float fac = exp2f(m[h] - tmax);
                    m[h] = tmax;
                    lacc[2 * h]     *= fac;
                    lacc[2 * h + 1] *= fac;
#pragma unroll
                    for (int ot = 0; ot < 16; ot++) {
                        oacc[ot][2 * h]     *= fac;
                        oacc[ot][2 * h + 1] *= fac;
                    }
                }
            }

            // exp via f16x2 MUFU, directly producing P fragment halves
            uint32_t ph[8][2];
#pragma unroll
            for (int nt = 0; nt < 8; nt++) {
                ph[nt][0] = h2exp2(f2h2(sacc[nt][0] - m[0], sacc[nt][1] - m[0]));
                ph[nt][1] = h2exp2(f2h2(sacc[nt][2] - m[1], sacc[nt][3] - m[1]));
            }

            // O += P V, and l += P · 1 (ones-MMA)
#pragma unroll
            for (int ks = 0; ks < 4; ks++) {
                uint32_t a[4];
                a[0] = ph[2 * ks][0];
                a[1] = ph[2 * ks][1];
                a[2] = ph[2 * ks + 1][0];
                a[3] = ph[2 * ks + 1][1];
                mma_f16(lacc, a, ONES, ONES);
#pragma unroll
                for (int np = 0; np < 8; np++) {
                    uint32_t bb[4];
                    ldsm_x4(bb, vA[hb] + (uint32_t)(np * 16 * 72 + ks * 16) * 2u);
                    mma_f16(oacc[2 * np], a, bb[0], bb[2]);
                    mma_f16(oacc[2 * np + 1], a, bb[1], bb[3]);
                }
            }
        }
    }

    // l comes straight from the ones-MMA accumulator (row sums, quad-uniform)
    float inv0 = 1.f / lacc[0], inv1 = 1.f / lacc[2];
    size_t row0 = (size_t)b * NQ_ + qbase + r0;
#pragma unroll
    for (int nt = 0; nt < 16; nt++) {
        int ci = nt * 8 + 2 * q4;
        *(uint32_t*)&d_yy[row0 * CI_ + ci] = f2h2(oacc[nt][0] * inv0, oacc[nt][1] * inv0);
        *(uint32_t*)&d_yy[(row0 + 8) * CI_ + ci] = f2h2(oacc[nt][2] * inv1, oacc[nt][3] * inv1);
    }
}

// ---------------------------------------------------------------------------
// Kernel D: wconv + BN + residual fp16. Same as R15.
// ---------------------------------------------------------------------------
__global__ void __launch_bounds__(256, 2) wconv_kernel(
        const float* __restrict__ x,
        const float* __restrict__ wb,
        const float* __restrict__ bng, const float* __restrict__ bnb,
        const float* __restrict__ bnm, const float* __restrict__ bnv,
        float* __restrict__ out) {
    extern __shared__ unsigned short smh[];
    const int b = blockIdx.z;
    const int cobase = blockIdx.y * 128;
    const int nbase = blockIdx.x * 64;
    const int tid = threadIdx.x;
    const int warp = tid >> 5, lane = tid & 31;
    const int g = lane >> 2, q4 = lane & 3;
    const int m0 = (warp >> 1) * 32;
    const int n0 = (warp & 1) * 32;
    const uint32_t smb = (uint32_t)__cvta_generic_to_shared(smh);
    const uint32_t WB[2] = {0u, 9216u}, YB[2] = {18432u, 23040u};
    const int fOff = FRAG_OFF(72);

    float acc[2][4][4];
#pragma unroll
    for (int i = 0; i < 2; i++)
#pragma unroll
        for (int j = 0; j < 4; j++)
#pragma unroll
            for (int k = 0; k < 4; k++) acc[i][j][k] = 0.f;

    const unsigned short* yb = d_yy + ((size_t)b * NQ_ + nbase) * CI_;

#pragma unroll
    for (int u = 0; u < 4; u++) {
        int idx = u * 256 + tid;
        int r = idx >> 3, c8 = idx & 7;
        cpa(smb + (WB[0] + r * 72 + c8 * 8) * 2u, &wwr[(cobase + r) * CI_ + c8 * 8]);
    }
#pragma unroll
    for (int u = 0; u < 2; u++) {
        int idx = u * 256 + tid;
        int r = idx >> 3, c8 = idx & 7;
        cpa(smb + (YB[0] + r * 72 + c8 * 8) * 2u, yb + (size_t)r * CI_ + c8 * 8);
    }
    CP_COMMIT();

    for (int ch = 0; ch < 2; ch++) {
        CP_WAIT0();
        __syncthreads();
        if (ch < 1) {
#pragma unroll
            for (int u = 0; u < 4; u++) {
                int idx = u * 256 + tid;
                int r = idx >> 3, c8 = idx & 7;
                cpa(smb + (WB[1] + r * 72 + c8 * 8) * 2u,
                    &wwr[(cobase + r) * CI_ + 64 + c8 * 8]);
            }
#pragma unroll
            for (int u = 0; u < 2; u++) {
                int idx = u * 256 + tid;
                int r = idx >> 3, c8 = idx & 7;
                cpa(smb + (YB[1] + r * 72 + c8 * 8) * 2u,
                    yb + (size_t)r * CI_ + 64 + c8 * 8);
            }
            CP_COMMIT();
        }
#pragma unroll
        for (int ks = 0; ks < 4; ks++) {
            uint32_t a[2][4];
#pragma unroll
            for (int mt = 0; mt < 2; mt++)
                ldsm_x4(a[mt], smb + (uint32_t)(WB[ch & 1] + (m0 + mt * 16) * 72
                                                + ks * 16 + fOff) * 2u);
#pragma unroll
            for (int np = 0; np < 2; np++) {
                uint32_t bb[4];
                ldsm_x4(bb, smb + (uint32_t)(YB[ch & 1] + (n0 + np * 16) * 72
                                             + ks * 16 + fOff) * 2u);
#pragma unroll
                for (int mt = 0; mt < 2; mt++) {
                    mma_f16(acc[mt][2 * np], a[mt], bb[0], bb[2]);
                    mma_f16(acc[mt][2 * np + 1], a[mt], bb[1], bb[3]);
                }
            }
        }
    }

    float sc[2][2], sh[2][2];
#pragma unroll
    for (int mt = 0; mt < 2; mt++)
#pragma unroll
        for (int h = 0; h < 2; h++) {
            int co = cobase + m0 + mt * 16 + g + h * 8;
            float s = bng[co] * rsqrtf(bnv[co] + 1e-5f);
            sc[mt][h] = s;
            sh[mt][h] = bnb[co] - bnm[co] * s + s * wb[co];
        }
#pragma unroll
    for (int mt = 0; mt < 2; mt++) {
#pragma unroll
        for (int j = 0; j < 4; j++) {
            int n = nbase + n0 + j * 8 + 2 * q4;
#pragma unroll
            for (int h = 0; h < 2; h++) {
                int co = cobase + m0 + mt * 16 + g + h * 8;
                size_t base = ((size_t)b * C_ + co) * NQ_ + n;
                float2 xv = *(const float2*)&x[base];
                float2 o;
                o.x = acc[mt][j][2 * h]     * sc[mt][h] + sh[mt][h] + xv.x;
                o.y = acc[mt][j][2 * h + 1] * sc[mt][h] + sh[mt][h] + xv.y;
                *(float2*)&out[base] = o;
            }
        }
    }
}

// ---------------------------------------------------------------------------
extern "C" void kernel_launch(void* const* d_in, const int* in_sizes, int n_in,
                              void* d_out, int out_size) {
    const float* x    = (const float*)d_in[0];
    const float* g_w  = (const float*)d_in[1];
    const float* g_b  = (const float*)d_in[2];
    const float* th_w = (const float*)d_in[3];
    const float* th_b = (const float*)d_in[4];
    const float* ph_w = (const float*)d_in[5];
    const float* ph_b = (const float*)d_in[6];
    const float* w_w  = (const float*)d_in[7];
    const float* w_b  = (const float*)d_in[8];
    const float* bn_g = (const float*)d_in[9];
    const float* bn_b = (const float*)d_in[10];
    const float* bn_m = (const float*)d_in[11];
    const float* bn_v = (const float*)d_in[12];
    float* out = (float*)d_out;

    const int smA = 27648 * 2;   // 55296
    const int smB = 27648 * 2;   // 55296
    const int smC = 53248 * 2;   // 106496
    const int smD = 27648 * 2;   // 55296

    cudaFuncSetAttribute(conv_theta_kernel, cudaFuncAttributeMaxDynamicSharedMemorySize, smA);
    cudaFuncSetAttribute(conv_gphi_kernel,  cudaFuncAttributeMaxDynamicSharedMemorySize, smB);
    cudaFuncSetAttribute(attn_kernel,       cudaFuncAttributeMaxDynamicSharedMemorySize, smC);
    cudaFuncSetAttribute(wconv_kernel,      cudaFuncAttributeMaxDynamicSharedMemorySize, smD);

    prep_kernel<<<dim3(128, 4, 5), 256>>>(x, th_w, g_w, ph_w, w_w);
    conv_theta_kernel<<<dim3(NQ_ / 64, B_), 256, smA>>>(th_b);
    conv_gphi_kernel<<<dim3(128, 2, B_), 256, smB>>>(g_b, ph_b);
    attn_kernel<<<dim3(NQ_ / 128, B_), 256, smC>>>();
    wconv_kernel<<<dim3(NQ_ / 64, 2, B_), 256, smD>>>(x, w_b,
                                                      bn_g, bn_b, bn_m, bn_v, out);
}